// round 6
// baseline (speedup 1.0000x reference)
#include <cuda_runtime.h>
#include <cuda_bf16.h>
#include <math.h>
#include <stdint.h>

// ---------------------------------------------------------------------------
// Problem constants
// ---------------------------------------------------------------------------
static constexpr int NT = 2048;      // tokens (B*L)
static constexpr int NH = 64;
static constexpr int NV = 32000;
static constexpr int KK = 448;       // 64 freq + 64 cos + 64 sin + 256 hidden

// GEMM tiling (mma.sync path)
static constexpr int CTA_M = 128;
static constexpr int CTA_N = 128;
static constexpr int KC    = 64;               // K per chunk
static constexpr int NCHUNK = KK / KC;         // 7

// SMEM stage layout (bytes). Rows are 128B (64 bf16), SW128-swizzled.
static constexpr int AH_BYTES = CTA_M * KC * 2;   // 16384
static constexpr int BH_BYTES = CTA_N * KC * 2;   // 16384
static constexpr int OFF_AH = 0;
static constexpr int OFF_AL = AH_BYTES;                    // 16384
static constexpr int OFF_BH = 2 * AH_BYTES;                // 32768
static constexpr int OFF_BL = 2 * AH_BYTES + BH_BYTES;     // 49152
static constexpr int STAGE_BYTES = 2 * AH_BYTES + 2 * BH_BYTES;  // 65536
static constexpr int SMEM_TOTAL = 2 * STAGE_BYTES;               // 131072

// ---------------------------------------------------------------------------
// Device scratch (allocation-free)
// ---------------------------------------------------------------------------
__device__ __nv_bfloat16 g_Ah[NT * KK];
__device__ __nv_bfloat16 g_Al[NT * KK];
__device__ __nv_bfloat16 g_Bh[(size_t)NV * KK];
__device__ __nv_bfloat16 g_Bl[(size_t)NV * KK];
__device__ float g_v2[NV];
__device__ float g_f2[NT];
__device__ float g_lamp[NT];

// ---------------------------------------------------------------------------
// Helpers
// ---------------------------------------------------------------------------
__device__ __forceinline__ uint32_t smem_u32(const void* p) {
    uint32_t a;
    asm("{ .reg .u64 t; cvta.to.shared.u64 t, %1; cvt.u32.u64 %0, t; }" : "=r"(a) : "l"(p));
    return a;
}

__device__ __forceinline__ void cpa16(uint32_t saddr, const void* gaddr) {
    asm volatile("cp.async.cg.shared.global [%0], [%1], 16;" :: "r"(saddr), "l"(gaddr));
}
#define CPA_COMMIT() asm volatile("cp.async.commit_group;" ::: "memory")
#define CPA_WAIT1()  asm volatile("cp.async.wait_group 1;" ::: "memory")
#define CPA_WAIT0()  asm volatile("cp.async.wait_group 0;" ::: "memory")

#define LDSM_X4(r, addr) \
    asm volatile("ldmatrix.sync.aligned.m8n8.x4.shared.b16 {%0,%1,%2,%3}, [%4];" \
        : "=r"((r)[0]), "=r"((r)[1]), "=r"((r)[2]), "=r"((r)[3]) : "r"(addr))

#define MMA16816(C, A, B0, B1) \
    asm volatile("mma.sync.aligned.m16n8k16.row.col.f32.bf16.bf16.f32 " \
        "{%0,%1,%2,%3}, {%4,%5,%6,%7}, {%8,%9}, {%0,%1,%2,%3};" \
        : "+f"((C)[0]), "+f"((C)[1]), "+f"((C)[2]), "+f"((C)[3]) \
        : "r"((A)[0]), "r"((A)[1]), "r"((A)[2]), "r"((A)[3]), "r"(B0), "r"(B1))

__device__ __forceinline__ float gelu_exact(float x) {
    return 0.5f * x * (1.0f + erff(x * 0.7071067811865476f));
}
__device__ __forceinline__ void split_store(float v, size_t idx,
                                            __nv_bfloat16* hi, __nv_bfloat16* lo) {
    __nv_bfloat16 h = __float2bfloat16(v);
    hi[idx] = h;
    lo[idx] = __float2bfloat16(v - __bfloat162float(h));
}

// ---------------------------------------------------------------------------
// Token prep: 4 tokens / block, 256 threads.  Writes A rows [t][448] hi/lo:
//   cols [0,64)=freq, [64,128)=cos(ph)*sc, [128,192)=sin(ph)*sc, [192,448)=0.1*x
//   sc = (0.5/64) * log1p(sum amps)
// ---------------------------------------------------------------------------
__global__ void token_prep(const float* __restrict__ wave,
                           const float* __restrict__ W0, const float* __restrict__ b0,
                           const float* __restrict__ W1, const float* __restrict__ b1,
                           const float* __restrict__ W2, const float* __restrict__ b2,
                           const float* __restrict__ rw)
{
    __shared__ float sw[4][192];
    __shared__ float sx[4][256];
    __shared__ float sy[4][256];
    __shared__ float slamp[4];

    const int t0 = blockIdx.x * 4;
    const int j  = threadIdx.x;

    for (int i = j; i < 4 * 192; i += 256) {
        int tok = i / 192, kk = i % 192;
        sw[tok][kk] = wave[(size_t)(t0 + tok) * 192 + kk];
    }
    __syncthreads();

    if (j < 8) {
        int tok = j & 3;
        if (j < 4) {
            float s = 0.f;
            for (int h = 0; h < NH; h++) { float f = sw[tok][h]; s += f * f; }
            g_f2[t0 + tok] = s;
        } else {
            float s = 0.f;
            for (int h = 0; h < NH; h++) s += sw[tok][64 + h];
            float l = log1pf(s);
            slamp[tok] = l;
            g_lamp[t0 + tok] = l;
        }
    }

    // layer 0: 192 -> 256
    float acc0 = 0.f, acc1 = 0.f, acc2 = 0.f, acc3 = 0.f;
    float bb = b0[j];
    for (int k = 0; k < 192; k++) {
        float w = W0[k * 256 + j];
        acc0 = fmaf(sw[0][k], w, acc0);
        acc1 = fmaf(sw[1][k], w, acc1);
        acc2 = fmaf(sw[2][k], w, acc2);
        acc3 = fmaf(sw[3][k], w, acc3);
    }
    __syncthreads();
    sx[0][j] = gelu_exact(acc0 + bb);
    sx[1][j] = gelu_exact(acc1 + bb);
    sx[2][j] = gelu_exact(acc2 + bb);
    sx[3][j] = gelu_exact(acc3 + bb);
    __syncthreads();

    bb = b1[j];
    float r1 = rw[1];
    acc0 = acc1 = acc2 = acc3 = 0.f;
    for (int k = 0; k < 256; k++) {
        float w = W1[k * 256 + j];
        acc0 = fmaf(sx[0][k], w, acc0);
        acc1 = fmaf(sx[1][k], w, acc1);
        acc2 = fmaf(sx[2][k], w, acc2);
        acc3 = fmaf(sx[3][k], w, acc3);
    }
    sy[0][j] = gelu_exact(acc0 + bb) + r1 * sx[0][j];
    sy[1][j] = gelu_exact(acc1 + bb) + r1 * sx[1][j];
    sy[2][j] = gelu_exact(acc2 + bb) + r1 * sx[2][j];
    sy[3][j] = gelu_exact(acc3 + bb) + r1 * sx[3][j];
    __syncthreads();

    bb = b2[j];
    float r2 = rw[2];
    acc0 = acc1 = acc2 = acc3 = 0.f;
    for (int k = 0; k < 256; k++) {
        float w = W2[k * 256 + j];
        acc0 = fmaf(sy[0][k], w, acc0);
        acc1 = fmaf(sy[1][k], w, acc1);
        acc2 = fmaf(sy[2][k], w, acc2);
        acc3 = fmaf(sy[3][k], w, acc3);
    }
    {
        float z[4];
        z[0] = 0.1f * (gelu_exact(acc0 + bb) + r2 * sy[0][j]);
        z[1] = 0.1f * (gelu_exact(acc1 + bb) + r2 * sy[1][j]);
        z[2] = 0.1f * (gelu_exact(acc2 + bb) + r2 * sy[2][j]);
        z[3] = 0.1f * (gelu_exact(acc3 + bb) + r2 * sy[3][j]);
        #pragma unroll
        for (int i = 0; i < 4; i++)
            split_store(z[i], (size_t)(t0 + i) * KK + 192 + j, g_Ah, g_Al);
    }

    {
        int i = j >> 6, h = j & 63;
        float f  = sw[i][h];
        float ph = sw[i][128 + h];
        float sc = 0.0078125f * slamp[i];
        float sn, cs;
        sincosf(ph, &sn, &cs);
        size_t base = (size_t)(t0 + i) * KK;
        split_store(f,       base + h,        g_Ah, g_Al);
        split_store(cs * sc, base + 64 + h,   g_Ah, g_Al);
        split_store(sn * sc, base + 128 + h,  g_Ah, g_Al);
    }
}

// ---------------------------------------------------------------------------
// Vocab prep
// ---------------------------------------------------------------------------
__global__ void vocab_v2_kernel(const float* __restrict__ vf)
{
    int v = blockIdx.x * 256 + threadIdx.x;
    if (v >= NV) return;
    const float* r = vf + (size_t)v * NH;
    float s = 0.f;
    #pragma unroll
    for (int h = 0; h < NH; h++) s = fmaf(r[h], r[h], s);
    g_v2[v] = s;
}

// B rows [v][448]: cols [0,64)=vf, [64,128)=cos(vp), [128,192)=sin(vp)
__global__ void vocab_feat(const float* __restrict__ vf, const float* __restrict__ vp)
{
    size_t idx = (size_t)blockIdx.x * 256 + threadIdx.x;   // v*64 + h
    if (idx >= (size_t)NV * NH) return;
    int v = (int)(idx >> 6), h = (int)(idx & 63);
    float f = vf[idx];
    float p = vp[idx];
    float sn, cs;
    sincosf(p, &sn, &cs);
    size_t base = (size_t)v * KK;
    split_store(f,  base + h,       g_Bh, g_Bl);
    split_store(cs, base + 64 + h,  g_Bh, g_Bl);
    split_store(sn, base + 128 + h, g_Bh, g_Bl);
}

// B cols [192,448) = Wv^T (Wv is [256][32000]) via tiled transpose
__global__ void wv_transpose(const float* __restrict__ Wv)
{
    __shared__ float st[32][33];
    const int v0 = blockIdx.x * 32;
    const int k0 = blockIdx.y * 32;
    const int tx = threadIdx.x, ty = threadIdx.y;   // (32, 8)
    #pragma unroll
    for (int r = 0; r < 4; r++)
        st[ty + r * 8][tx] = Wv[(size_t)(k0 + ty + r * 8) * NV + v0 + tx];
    __syncthreads();
    #pragma unroll
    for (int r = 0; r < 4; r++) {
        int v = v0 + ty + r * 8, k = k0 + tx;
        split_store(st[tx][ty + r * 8], (size_t)v * KK + 192 + k, g_Bh, g_Bl);
    }
}

// ---------------------------------------------------------------------------
// Main GEMM on mma.sync.m16n8k16 (bf16 3-product split).
// CTA 128x128, 8 warps (2M x 4N), warp tile 64x32.
// Chunk 0 = cross term; in-register transform after it; chunks 1..6 add the
// linear terms (0.5*coh*lam + 0.1*synth) on top.
// ---------------------------------------------------------------------------
__global__ void __launch_bounds__(256, 1)
spectral_hmma(const float* __restrict__ bv, float* __restrict__ out)
{
    extern __shared__ char smem[];
    const uint32_t sbase = smem_u32(smem);

    const int tid = threadIdx.x;
    const int wid = tid >> 5;
    const int lid = tid & 31;
    const int wm = wid & 1;          // M offset wm*64
    const int wn = wid >> 1;         // 0..3 -> N offset wn*32
    const int v0 = blockIdx.x * CTA_N;
    const int m0 = blockIdx.y * CTA_M;

    // lane-derived ldmatrix address components
    const int a_row = lid & 15;                       // row within 16-row tile
    const int a_c16 = (lid >> 4) & 1;                 // k half (16B units)
    const int b_row = ((lid >> 4) & 1) * 8 + (lid & 7);
    const int b_c16 = (lid >> 3) & 1;

    float acc[4][4][4];
    #pragma unroll
    for (int mt = 0; mt < 4; mt++)
        #pragma unroll
        for (int nt = 0; nt < 4; nt++)
            #pragma unroll
            for (int e = 0; e < 4; e++) acc[mt][nt][e] = 0.f;

    auto load_stage = [&](int stage, int kc) {
        const uint32_t sb = sbase + stage * STAGE_BYTES;
        // A hi/lo: 128 rows x 128B -> 1024 16B units each
        #pragma unroll
        for (int i = 0; i < 4; i++) {
            int idx = tid + i * 256;
            int r = idx >> 3, u = idx & 7;
            uint32_t so = (uint32_t)(r * 128 + ((u * 16) ^ ((r & 7) << 4)));
            size_t go = (size_t)(m0 + r) * KK + kc + u * 8;
            cpa16(sb + OFF_AH + so, g_Ah + go);
            cpa16(sb + OFF_AL + so, g_Al + go);
        }
        // B hi/lo: 128 rows x 128B -> 1024 units each
        #pragma unroll
        for (int i = 0; i < 4; i++) {
            int idx = tid + i * 256;
            int r = idx >> 3, u = idx & 7;
            uint32_t so = (uint32_t)(r * 128 + ((u * 16) ^ ((r & 7) << 4)));
            size_t go = (size_t)(v0 + r) * KK + kc + u * 8;
            cpa16(sb + OFF_BH + so, g_Bh + go);
            cpa16(sb + OFF_BL + so, g_Bl + go);
        }
        CPA_COMMIT();
    };

    load_stage(0, 0);

    #pragma unroll 1
    for (int c = 0; c < NCHUNK; c++) {
        if (c < NCHUNK - 1) { load_stage((c + 1) & 1, (c + 1) * KC); CPA_WAIT1(); }
        else                { CPA_WAIT0(); }
        __syncthreads();

        const uint32_t sb = sbase + (c & 1) * STAGE_BYTES;

        #pragma unroll
        for (int ks = 0; ks < 4; ks++) {
            uint32_t ah[4][4], al[4][4], bh[2][4], bl[2][4];
            #pragma unroll
            for (int mt = 0; mt < 4; mt++) {
                int R = wm * 64 + mt * 16 + a_row;
                uint32_t off = (uint32_t)(R * 128 + ((ks * 32 + a_c16 * 16) ^ ((R & 7) << 4)));
                LDSM_X4(ah[mt], sb + OFF_AH + off);
                LDSM_X4(al[mt], sb + OFF_AL + off);
            }
            #pragma unroll
            for (int ng = 0; ng < 2; ng++) {
                int R = wn * 32 + ng * 16 + b_row;
                uint32_t off = (uint32_t)(R * 128 + ((ks * 32 + b_c16 * 16) ^ ((R & 7) << 4)));
                LDSM_X4(bh[ng], sb + OFF_BH + off);
                LDSM_X4(bl[ng], sb + OFF_BL + off);
            }
            #pragma unroll
            for (int mt = 0; mt < 4; mt++)
                #pragma unroll
                for (int nt = 0; nt < 4; nt++) {
                    int ng = nt >> 1, sub = nt & 1;
                    MMA16816(acc[mt][nt], ah[mt], bh[ng][sub * 2], bh[ng][sub * 2 + 1]);
                    MMA16816(acc[mt][nt], ah[mt], bl[ng][sub * 2], bl[ng][sub * 2 + 1]);
                    MMA16816(acc[mt][nt], al[mt], bh[ng][sub * 2], bh[ng][sub * 2 + 1]);
                }
        }

        if (c == 0) {
            // acc currently = cross = <freq, vocab_freq>.  Transform:
            //   acc <- 0.1*bv[col] - sqrt(max(f2[row]+v2[col]-2*acc, 0))*lam[row]
            #pragma unroll
            for (int mt = 0; mt < 4; mt++) {
                int r0 = m0 + wm * 64 + mt * 16 + (lid >> 2);
                int r1 = r0 + 8;
                float f2a = g_f2[r0],  lma = g_lamp[r0];
                float f2b = g_f2[r1],  lmb = g_lamp[r1];
                #pragma unroll
                for (int nt = 0; nt < 4; nt++) {
                    int c0 = v0 + wn * 32 + (nt >> 1) * 16 + (nt & 1) * 8 + 2 * (lid & 3);
                    float v2x = g_v2[c0],     bvx = 0.1f * bv[c0];
                    float v2y = g_v2[c0 + 1], bvy = 0.1f * bv[c0 + 1];
                    float* a = acc[mt][nt];
                    a[0] = bvx - sqrtf(fmaxf(f2a + v2x - 2.f * a[0], 0.f)) * lma;
                    a[1] = bvy - sqrtf(fmaxf(f2a + v2y - 2.f * a[1], 0.f)) * lma;
                    a[2] = bvx - sqrtf(fmaxf(f2b + v2x - 2.f * a[2], 0.f)) * lmb;
                    a[3] = bvy - sqrtf(fmaxf(f2b + v2y - 2.f * a[3], 0.f)) * lmb;
                }
            }
        }
        __syncthreads();
    }

    // Writeout
    #pragma unroll
    for (int mt = 0; mt < 4; mt++) {
        size_t r0 = (size_t)(m0 + wm * 64 + mt * 16 + (lid >> 2));
        #pragma unroll
        for (int nt = 0; nt < 4; nt++) {
            int c0 = v0 + wn * 32 + (nt >> 1) * 16 + (nt & 1) * 8 + 2 * (lid & 3);
            float2 lo = make_float2(acc[mt][nt][0], acc[mt][nt][1]);
            float2 hi = make_float2(acc[mt][nt][2], acc[mt][nt][3]);
            *(float2*)(out + r0 * NV + c0)       = lo;
            *(float2*)(out + (r0 + 8) * NV + c0) = hi;
        }
    }
}

// ---------------------------------------------------------------------------
extern "C" void kernel_launch(void* const* d_in, const int* in_sizes, int n_in,
                              void* d_out, int out_size)
{
    const float* wave = (const float*)d_in[0];   // (2,1024,192)
    const float* vf   = (const float*)d_in[1];   // (32000,64)
    const float* vp   = (const float*)d_in[2];   // (32000,64)
    const float* W0   = (const float*)d_in[3];   // (192,256)
    const float* b0   = (const float*)d_in[4];
    const float* W1   = (const float*)d_in[5];   // (256,256)
    const float* b1   = (const float*)d_in[6];
    const float* W2   = (const float*)d_in[7];   // (256,256)
    const float* b2   = (const float*)d_in[8];
    const float* Wv   = (const float*)d_in[9];   // (256,32000)
    const float* bv   = (const float*)d_in[10];  // (32000,)
    const float* rw   = (const float*)d_in[11];  // (3,)
    float* out = (float*)d_out;

    cudaFuncSetAttribute(spectral_hmma,
                         cudaFuncAttributeMaxDynamicSharedMemorySize, SMEM_TOTAL);

    token_prep<<<NT / 4, 256>>>(wave, W0, b0, W1, b1, W2, b2, rw);
    vocab_v2_kernel<<<(NV + 255) / 256, 256>>>(vf);
    vocab_feat<<<(int)(((size_t)NV * NH + 255) / 256), 256>>>(vf, vp);
    wv_transpose<<<dim3(NV / 32, 256 / 32), dim3(32, 8)>>>(Wv);
    spectral_hmma<<<dim3(NV / CTA_N, NT / CTA_M), 256, SMEM_TOTAL>>>(bv, out);
}

// round 7
// speedup vs baseline: 1.1060x; 1.1060x over previous
#include <cuda_runtime.h>
#include <cuda_bf16.h>
#include <math.h>
#include <stdint.h>

// ---------------------------------------------------------------------------
// Problem constants
// ---------------------------------------------------------------------------
static constexpr int NT = 2048;      // tokens (B*L)
static constexpr int NH = 64;
static constexpr int NV = 32000;
static constexpr int KK = 448;       // 64 freq + 64 cos + 64 sin + 256 hidden

// GEMM tiling (mma.sync path)
static constexpr int CTA_M = 128;
static constexpr int CTA_N = 64;
static constexpr int KC    = 64;               // K per chunk
static constexpr int NCHUNK = KK / KC;         // 7
static constexpr int NTHR   = 128;             // 4 warps per CTA

// SMEM stage layout (bytes). Rows are 128B (64 bf16), SW128-swizzled.
static constexpr int AH_BYTES = CTA_M * KC * 2;   // 16384
static constexpr int BH_BYTES = CTA_N * KC * 2;   // 8192
static constexpr int OFF_AH = 0;
static constexpr int OFF_AL = AH_BYTES;                    // 16384
static constexpr int OFF_BH = 2 * AH_BYTES;                // 32768
static constexpr int OFF_BL = 2 * AH_BYTES + BH_BYTES;     // 40960
static constexpr int STAGE_BYTES = 2 * AH_BYTES + 2 * BH_BYTES;  // 49152
static constexpr int SMEM_TOTAL = 2 * STAGE_BYTES;               // 98304 (2 CTAs/SM)

// ---------------------------------------------------------------------------
// Device scratch (allocation-free)
// ---------------------------------------------------------------------------
__device__ __nv_bfloat16 g_Ah[NT * KK];
__device__ __nv_bfloat16 g_Al[NT * KK];
__device__ __nv_bfloat16 g_Bh[(size_t)NV * KK];
__device__ __nv_bfloat16 g_Bl[(size_t)NV * KK];
__device__ float g_v2[NV];
__device__ float g_f2[NT];
__device__ float g_lamp[NT];

// ---------------------------------------------------------------------------
// Helpers
// ---------------------------------------------------------------------------
__device__ __forceinline__ uint32_t smem_u32(const void* p) {
    uint32_t a;
    asm("{ .reg .u64 t; cvta.to.shared.u64 t, %1; cvt.u32.u64 %0, t; }" : "=r"(a) : "l"(p));
    return a;
}

__device__ __forceinline__ void cpa16(uint32_t saddr, const void* gaddr) {
    asm volatile("cp.async.cg.shared.global [%0], [%1], 16;" :: "r"(saddr), "l"(gaddr));
}
#define CPA_COMMIT() asm volatile("cp.async.commit_group;" ::: "memory")
#define CPA_WAIT1()  asm volatile("cp.async.wait_group 1;" ::: "memory")
#define CPA_WAIT0()  asm volatile("cp.async.wait_group 0;" ::: "memory")

#define LDSM_X4(r, addr) \
    asm volatile("ldmatrix.sync.aligned.m8n8.x4.shared.b16 {%0,%1,%2,%3}, [%4];" \
        : "=r"((r)[0]), "=r"((r)[1]), "=r"((r)[2]), "=r"((r)[3]) : "r"(addr))

#define MMA16816(C, A, B0, B1) \
    asm volatile("mma.sync.aligned.m16n8k16.row.col.f32.bf16.bf16.f32 " \
        "{%0,%1,%2,%3}, {%4,%5,%6,%7}, {%8,%9}, {%0,%1,%2,%3};" \
        : "+f"((C)[0]), "+f"((C)[1]), "+f"((C)[2]), "+f"((C)[3]) \
        : "r"((A)[0]), "r"((A)[1]), "r"((A)[2]), "r"((A)[3]), "r"(B0), "r"(B1))

__device__ __forceinline__ float gelu_exact(float x) {
    return 0.5f * x * (1.0f + erff(x * 0.7071067811865476f));
}
__device__ __forceinline__ void split_store(float v, size_t idx,
                                            __nv_bfloat16* hi, __nv_bfloat16* lo) {
    __nv_bfloat16 h = __float2bfloat16(v);
    hi[idx] = h;
    lo[idx] = __float2bfloat16(v - __bfloat162float(h));
}

// ---------------------------------------------------------------------------
// Token prep: 4 tokens / block, 256 threads.  Writes A rows [t][448] hi/lo:
//   cols [0,64)=freq, [64,128)=cos(ph)*sc, [128,192)=sin(ph)*sc, [192,448)=0.1*x
//   sc = (0.5/64) * log1p(sum amps)
// ---------------------------------------------------------------------------
__global__ void token_prep(const float* __restrict__ wave,
                           const float* __restrict__ W0, const float* __restrict__ b0,
                           const float* __restrict__ W1, const float* __restrict__ b1,
                           const float* __restrict__ W2, const float* __restrict__ b2,
                           const float* __restrict__ rw)
{
    __shared__ float sw[4][192];
    __shared__ float sx[4][256];
    __shared__ float sy[4][256];
    __shared__ float slamp[4];

    const int t0 = blockIdx.x * 4;
    const int j  = threadIdx.x;

    for (int i = j; i < 4 * 192; i += 256) {
        int tok = i / 192, kk = i % 192;
        sw[tok][kk] = wave[(size_t)(t0 + tok) * 192 + kk];
    }
    __syncthreads();

    if (j < 8) {
        int tok = j & 3;
        if (j < 4) {
            float s = 0.f;
            for (int h = 0; h < NH; h++) { float f = sw[tok][h]; s += f * f; }
            g_f2[t0 + tok] = s;
        } else {
            float s = 0.f;
            for (int h = 0; h < NH; h++) s += sw[tok][64 + h];
            float l = log1pf(s);
            slamp[tok] = l;
            g_lamp[t0 + tok] = l;
        }
    }

    // layer 0: 192 -> 256
    float acc0 = 0.f, acc1 = 0.f, acc2 = 0.f, acc3 = 0.f;
    float bb = b0[j];
    for (int k = 0; k < 192; k++) {
        float w = W0[k * 256 + j];
        acc0 = fmaf(sw[0][k], w, acc0);
        acc1 = fmaf(sw[1][k], w, acc1);
        acc2 = fmaf(sw[2][k], w, acc2);
        acc3 = fmaf(sw[3][k], w, acc3);
    }
    __syncthreads();
    sx[0][j] = gelu_exact(acc0 + bb);
    sx[1][j] = gelu_exact(acc1 + bb);
    sx[2][j] = gelu_exact(acc2 + bb);
    sx[3][j] = gelu_exact(acc3 + bb);
    __syncthreads();

    bb = b1[j];
    float r1 = rw[1];
    acc0 = acc1 = acc2 = acc3 = 0.f;
    for (int k = 0; k < 256; k++) {
        float w = W1[k * 256 + j];
        acc0 = fmaf(sx[0][k], w, acc0);
        acc1 = fmaf(sx[1][k], w, acc1);
        acc2 = fmaf(sx[2][k], w, acc2);
        acc3 = fmaf(sx[3][k], w, acc3);
    }
    sy[0][j] = gelu_exact(acc0 + bb) + r1 * sx[0][j];
    sy[1][j] = gelu_exact(acc1 + bb) + r1 * sx[1][j];
    sy[2][j] = gelu_exact(acc2 + bb) + r1 * sx[2][j];
    sy[3][j] = gelu_exact(acc3 + bb) + r1 * sx[3][j];
    __syncthreads();

    bb = b2[j];
    float r2 = rw[2];
    acc0 = acc1 = acc2 = acc3 = 0.f;
    for (int k = 0; k < 256; k++) {
        float w = W2[k * 256 + j];
        acc0 = fmaf(sy[0][k], w, acc0);
        acc1 = fmaf(sy[1][k], w, acc1);
        acc2 = fmaf(sy[2][k], w, acc2);
        acc3 = fmaf(sy[3][k], w, acc3);
    }
    {
        float z[4];
        z[0] = 0.1f * (gelu_exact(acc0 + bb) + r2 * sy[0][j]);
        z[1] = 0.1f * (gelu_exact(acc1 + bb) + r2 * sy[1][j]);
        z[2] = 0.1f * (gelu_exact(acc2 + bb) + r2 * sy[2][j]);
        z[3] = 0.1f * (gelu_exact(acc3 + bb) + r2 * sy[3][j]);
        #pragma unroll
        for (int i = 0; i < 4; i++)
            split_store(z[i], (size_t)(t0 + i) * KK + 192 + j, g_Ah, g_Al);
    }

    {
        int i = j >> 6, h = j & 63;
        float f  = sw[i][h];
        float ph = sw[i][128 + h];
        float sc = 0.0078125f * slamp[i];
        float sn, cs;
        sincosf(ph, &sn, &cs);
        size_t base = (size_t)(t0 + i) * KK;
        split_store(f,       base + h,        g_Ah, g_Al);
        split_store(cs * sc, base + 64 + h,   g_Ah, g_Al);
        split_store(sn * sc, base + 128 + h,  g_Ah, g_Al);
    }
}

// ---------------------------------------------------------------------------
// Vocab prep
// ---------------------------------------------------------------------------
__global__ void vocab_v2_kernel(const float* __restrict__ vf)
{
    int v = blockIdx.x * 256 + threadIdx.x;
    if (v >= NV) return;
    const float* r = vf + (size_t)v * NH;
    float s = 0.f;
    #pragma unroll
    for (int h = 0; h < NH; h++) s = fmaf(r[h], r[h], s);
    g_v2[v] = s;
}

// B rows [v][448]: cols [0,64)=vf, [64,128)=cos(vp), [128,192)=sin(vp)
__global__ void vocab_feat(const float* __restrict__ vf, const float* __restrict__ vp)
{
    size_t idx = (size_t)blockIdx.x * 256 + threadIdx.x;   // v*64 + h
    if (idx >= (size_t)NV * NH) return;
    int v = (int)(idx >> 6), h = (int)(idx & 63);
    float f = vf[idx];
    float p = vp[idx];
    float sn, cs;
    sincosf(p, &sn, &cs);
    size_t base = (size_t)v * KK;
    split_store(f,  base + h,       g_Bh, g_Bl);
    split_store(cs, base + 64 + h,  g_Bh, g_Bl);
    split_store(sn, base + 128 + h, g_Bh, g_Bl);
}

// B cols [192,448) = Wv^T (Wv is [256][32000]) via tiled transpose
__global__ void wv_transpose(const float* __restrict__ Wv)
{
    __shared__ float st[32][33];
    const int v0 = blockIdx.x * 32;
    const int k0 = blockIdx.y * 32;
    const int tx = threadIdx.x, ty = threadIdx.y;   // (32, 8)
    #pragma unroll
    for (int r = 0; r < 4; r++)
        st[ty + r * 8][tx] = Wv[(size_t)(k0 + ty + r * 8) * NV + v0 + tx];
    __syncthreads();
    #pragma unroll
    for (int r = 0; r < 4; r++) {
        int v = v0 + ty + r * 8, k = k0 + tx;
        split_store(st[tx][ty + r * 8], (size_t)v * KK + 192 + k, g_Bh, g_Bl);
    }
}

// ---------------------------------------------------------------------------
// Main GEMM on mma.sync.m16n8k16 (bf16 3-product split).
// CTA 128x64, 4 warps (2M x 2N), warp tile 64x32 -> 48 MMA : 12 LDSM per k16.
// 96KB smem/CTA -> 2 CTAs/SM for bubble-filling.
// Chunk 0 = cross term; in-register transform after it; chunks 1..6 add the
// linear terms (0.5*coh*lam + 0.1*synth) on top.
// ---------------------------------------------------------------------------
__global__ void __launch_bounds__(NTHR, 2)
spectral_hmma(const float* __restrict__ bv, float* __restrict__ out)
{
    extern __shared__ char smem[];
    const uint32_t sbase = smem_u32(smem);

    const int tid = threadIdx.x;
    const int wid = tid >> 5;
    const int lid = tid & 31;
    const int wm = wid & 1;          // M offset wm*64
    const int wn = wid >> 1;         // 0..1 -> N offset wn*32
    const int v0 = blockIdx.x * CTA_N;
    const int m0 = blockIdx.y * CTA_M;

    // lane-derived ldmatrix address components
    const int a_row = lid & 15;                       // row within 16-row tile
    const int a_c16 = (lid >> 4) & 1;                 // k half (16B units)
    const int b_row = ((lid >> 4) & 1) * 8 + (lid & 7);
    const int b_c16 = (lid >> 3) & 1;

    float acc[4][4][4];
    #pragma unroll
    for (int mt = 0; mt < 4; mt++)
        #pragma unroll
        for (int nt = 0; nt < 4; nt++)
            #pragma unroll
            for (int e = 0; e < 4; e++) acc[mt][nt][e] = 0.f;

    auto load_stage = [&](int stage, int kc) {
        const uint32_t sb = sbase + stage * STAGE_BYTES;
        // A hi/lo: 128 rows x 128B -> 1024 16B units each
        #pragma unroll
        for (int i = 0; i < 8; i++) {
            int idx = tid + i * NTHR;
            int r = idx >> 3, u = idx & 7;
            uint32_t so = (uint32_t)(r * 128 + ((u * 16) ^ ((r & 7) << 4)));
            size_t go = (size_t)(m0 + r) * KK + kc + u * 8;
            cpa16(sb + OFF_AH + so, g_Ah + go);
            cpa16(sb + OFF_AL + so, g_Al + go);
        }
        // B hi/lo: 64 rows x 128B -> 512 units each
        #pragma unroll
        for (int i = 0; i < 4; i++) {
            int idx = tid + i * NTHR;
            int r = idx >> 3, u = idx & 7;
            uint32_t so = (uint32_t)(r * 128 + ((u * 16) ^ ((r & 7) << 4)));
            size_t go = (size_t)(v0 + r) * KK + kc + u * 8;
            cpa16(sb + OFF_BH + so, g_Bh + go);
            cpa16(sb + OFF_BL + so, g_Bl + go);
        }
        CPA_COMMIT();
    };

    load_stage(0, 0);

    #pragma unroll 1
    for (int c = 0; c < NCHUNK; c++) {
        if (c < NCHUNK - 1) { load_stage((c + 1) & 1, (c + 1) * KC); CPA_WAIT1(); }
        else                { CPA_WAIT0(); }
        __syncthreads();

        const uint32_t sb = sbase + (c & 1) * STAGE_BYTES;

        #pragma unroll
        for (int ks = 0; ks < 4; ks++) {
            uint32_t ah[4][4], al[4][4], bh[2][4], bl[2][4];
            #pragma unroll
            for (int mt = 0; mt < 4; mt++) {
                int R = wm * 64 + mt * 16 + a_row;
                uint32_t off = (uint32_t)(R * 128 + ((ks * 32 + a_c16 * 16) ^ ((R & 7) << 4)));
                LDSM_X4(ah[mt], sb + OFF_AH + off);
                LDSM_X4(al[mt], sb + OFF_AL + off);
            }
            #pragma unroll
            for (int ng = 0; ng < 2; ng++) {
                int R = wn * 32 + ng * 16 + b_row;
                uint32_t off = (uint32_t)(R * 128 + ((ks * 32 + b_c16 * 16) ^ ((R & 7) << 4)));
                LDSM_X4(bh[ng], sb + OFF_BH + off);
                LDSM_X4(bl[ng], sb + OFF_BL + off);
            }
            #pragma unroll
            for (int mt = 0; mt < 4; mt++)
                #pragma unroll
                for (int nt = 0; nt < 4; nt++) {
                    int ng = nt >> 1, sub = nt & 1;
                    MMA16816(acc[mt][nt], ah[mt], bh[ng][sub * 2], bh[ng][sub * 2 + 1]);
                    MMA16816(acc[mt][nt], ah[mt], bl[ng][sub * 2], bl[ng][sub * 2 + 1]);
                    MMA16816(acc[mt][nt], al[mt], bh[ng][sub * 2], bh[ng][sub * 2 + 1]);
                }
        }

        if (c == 0) {
            // acc currently = cross = <freq, vocab_freq>.  Transform:
            //   acc <- 0.1*bv[col] - sqrt(max(f2[row]+v2[col]-2*acc, 0))*lam[row]
            #pragma unroll
            for (int mt = 0; mt < 4; mt++) {
                int r0 = m0 + wm * 64 + mt * 16 + (lid >> 2);
                int r1 = r0 + 8;
                float f2a = g_f2[r0],  lma = g_lamp[r0];
                float f2b = g_f2[r1],  lmb = g_lamp[r1];
                #pragma unroll
                for (int nt = 0; nt < 4; nt++) {
                    int c0 = v0 + wn * 32 + (nt >> 1) * 16 + (nt & 1) * 8 + 2 * (lid & 3);
                    float v2x = g_v2[c0],     bvx = 0.1f * bv[c0];
                    float v2y = g_v2[c0 + 1], bvy = 0.1f * bv[c0 + 1];
                    float* a = acc[mt][nt];
                    a[0] = bvx - sqrtf(fmaxf(f2a + v2x - 2.f * a[0], 0.f)) * lma;
                    a[1] = bvy - sqrtf(fmaxf(f2a + v2y - 2.f * a[1], 0.f)) * lma;
                    a[2] = bvx - sqrtf(fmaxf(f2b + v2x - 2.f * a[2], 0.f)) * lmb;
                    a[3] = bvy - sqrtf(fmaxf(f2b + v2y - 2.f * a[3], 0.f)) * lmb;
                }
            }
        }
        __syncthreads();
    }

    // Writeout
    #pragma unroll
    for (int mt = 0; mt < 4; mt++) {
        size_t r0 = (size_t)(m0 + wm * 64 + mt * 16 + (lid >> 2));
        #pragma unroll
        for (int nt = 0; nt < 4; nt++) {
            int c0 = v0 + wn * 32 + (nt >> 1) * 16 + (nt & 1) * 8 + 2 * (lid & 3);
            float2 lo = make_float2(acc[mt][nt][0], acc[mt][nt][1]);
            float2 hi = make_float2(acc[mt][nt][2], acc[mt][nt][3]);
            *(float2*)(out + r0 * NV + c0)       = lo;
            *(float2*)(out + (r0 + 8) * NV + c0) = hi;
        }
    }
}

// ---------------------------------------------------------------------------
extern "C" void kernel_launch(void* const* d_in, const int* in_sizes, int n_in,
                              void* d_out, int out_size)
{
    const float* wave = (const float*)d_in[0];   // (2,1024,192)
    const float* vf   = (const float*)d_in[1];   // (32000,64)
    const float* vp   = (const float*)d_in[2];   // (32000,64)
    const float* W0   = (const float*)d_in[3];   // (192,256)
    const float* b0   = (const float*)d_in[4];
    const float* W1   = (const float*)d_in[5];   // (256,256)
    const float* b1   = (const float*)d_in[6];
    const float* W2   = (const float*)d_in[7];   // (256,256)
    const float* b2   = (const float*)d_in[8];
    const float* Wv   = (const float*)d_in[9];   // (256,32000)
    const float* bv   = (const float*)d_in[10];  // (32000,)
    const float* rw   = (const float*)d_in[11];  // (3,)
    float* out = (float*)d_out;

    cudaFuncSetAttribute(spectral_hmma,
                         cudaFuncAttributeMaxDynamicSharedMemorySize, STAGE_BYTES * 2);

    token_prep<<<NT / 4, 256>>>(wave, W0, b0, W1, b1, W2, b2, rw);
    vocab_v2_kernel<<<(NV + 255) / 256, 256>>>(vf);
    vocab_feat<<<(int)(((size_t)NV * NH + 255) / 256), 256>>>(vf, vp);
    wv_transpose<<<dim3(NV / 32, 256 / 32), dim3(32, 8)>>>(Wv);
    spectral_hmma<<<dim3(NV / CTA_N, NT / CTA_M), NTHR, SMEM_TOTAL>>>(bv, out);
}

// round 10
// speedup vs baseline: 1.7106x; 1.5466x over previous
#include <cuda_runtime.h>
#include <cuda_bf16.h>
#include <math.h>
#include <stdint.h>

// ---------------------------------------------------------------------------
// Problem constants
// ---------------------------------------------------------------------------
static constexpr int NT = 2048;      // tokens (B*L)
static constexpr int NH = 64;
static constexpr int NV = 32000;
static constexpr int KK = 448;       // 64 freq + 64 cos + 64 sin + 256 hidden

// GEMM tiling (mma.sync path) — R5 champion shape
static constexpr int CTA_M = 128;
static constexpr int CTA_N = 64;
static constexpr int KC    = 64;               // K per chunk
static constexpr int NCHUNK = KK / KC;         // 7

// SMEM stage layout (bytes). Rows are 128B (64 bf16), SW128-swizzled.
// Chunk 0 uses all four planes; chunks 1-6 use only AH/BH.
static constexpr int AH_BYTES = CTA_M * KC * 2;   // 16384
static constexpr int BH_BYTES = CTA_N * KC * 2;   // 8192
static constexpr int OFF_AH = 0;
static constexpr int OFF_AL = AH_BYTES;                    // 16384
static constexpr int OFF_BH = 2 * AH_BYTES;                // 32768
static constexpr int OFF_BL = 2 * AH_BYTES + BH_BYTES;     // 40960
static constexpr int STAGE_BYTES = 2 * AH_BYTES + 2 * BH_BYTES;  // 49152
static constexpr int SMEM_TOTAL = 2 * STAGE_BYTES;               // 98304 (2 CTAs/SM)

// ---------------------------------------------------------------------------
// Device scratch (allocation-free).  lo planes exist only for K in [0,64).
// ---------------------------------------------------------------------------
__device__ __nv_bfloat16 g_Ah[NT * KK];
__device__ __nv_bfloat16 g_Al[NT * 64];
__device__ __nv_bfloat16 g_Bh[(size_t)NV * KK];
__device__ __nv_bfloat16 g_Bl[(size_t)NV * 64];
__device__ float g_v2[NV];
__device__ float g_f2[NT];
__device__ float g_lamp[NT];

// ---------------------------------------------------------------------------
// Helpers
// ---------------------------------------------------------------------------
__device__ __forceinline__ uint32_t smem_u32(const void* p) {
    uint32_t a;
    asm("{ .reg .u64 t; cvta.to.shared.u64 t, %1; cvt.u32.u64 %0, t; }" : "=r"(a) : "l"(p));
    return a;
}

__device__ __forceinline__ void cpa16(uint32_t saddr, const void* gaddr) {
    asm volatile("cp.async.cg.shared.global [%0], [%1], 16;" :: "r"(saddr), "l"(gaddr));
}
#define CPA_COMMIT() asm volatile("cp.async.commit_group;" ::: "memory")
#define CPA_WAIT1()  asm volatile("cp.async.wait_group 1;" ::: "memory")
#define CPA_WAIT0()  asm volatile("cp.async.wait_group 0;" ::: "memory")

#define LDSM_X4(r, addr) \
    asm volatile("ldmatrix.sync.aligned.m8n8.x4.shared.b16 {%0,%1,%2,%3}, [%4];" \
        : "=r"((r)[0]), "=r"((r)[1]), "=r"((r)[2]), "=r"((r)[3]) : "r"(addr))

#define MMA16816(C, A, B0, B1) \
    asm volatile("mma.sync.aligned.m16n8k16.row.col.f32.bf16.bf16.f32 " \
        "{%0,%1,%2,%3}, {%4,%5,%6,%7}, {%8,%9}, {%0,%1,%2,%3};" \
        : "+f"((C)[0]), "+f"((C)[1]), "+f"((C)[2]), "+f"((C)[3]) \
        : "r"((A)[0]), "r"((A)[1]), "r"((A)[2]), "r"((A)[3]), "r"(B0), "r"(B1))

__device__ __forceinline__ float gelu_exact(float x) {
    return 0.5f * x * (1.0f + erff(x * 0.7071067811865476f));
}

// ---------------------------------------------------------------------------
// Token prep: 4 tokens / block, 256 threads.  Writes A rows [t][448]:
//   cols [0,64)=freq (hi + lo), [64,128)=cos(ph)*sc (hi), [128,192)=sin(ph)*sc (hi),
//   [192,448)=0.1*x (hi).   sc = (0.5/64) * log1p(sum amps)
// ---------------------------------------------------------------------------
__global__ void token_prep(const float* __restrict__ wave,
                           const float* __restrict__ W0, const float* __restrict__ b0,
                           const float* __restrict__ W1, const float* __restrict__ b1,
                           const float* __restrict__ W2, const float* __restrict__ b2,
                           const float* __restrict__ rw)
{
    __shared__ float sw[4][192];
    __shared__ float sx[4][256];
    __shared__ float sy[4][256];
    __shared__ float slamp[4];

    const int t0 = blockIdx.x * 4;
    const int j  = threadIdx.x;

    for (int i = j; i < 4 * 192; i += 256) {
        int tok = i / 192, kk = i % 192;
        sw[tok][kk] = wave[(size_t)(t0 + tok) * 192 + kk];
    }
    __syncthreads();

    if (j < 8) {
        int tok = j & 3;
        if (j < 4) {
            float s = 0.f;
            for (int h = 0; h < NH; h++) { float f = sw[tok][h]; s += f * f; }
            g_f2[t0 + tok] = s;
        } else {
            float s = 0.f;
            for (int h = 0; h < NH; h++) s += sw[tok][64 + h];
            float l = log1pf(s);
            slamp[tok] = l;
            g_lamp[t0 + tok] = l;
        }
    }

    // layer 0: 192 -> 256
    float acc0 = 0.f, acc1 = 0.f, acc2 = 0.f, acc3 = 0.f;
    float bb = b0[j];
    for (int k = 0; k < 192; k++) {
        float w = W0[k * 256 + j];
        acc0 = fmaf(sw[0][k], w, acc0);
        acc1 = fmaf(sw[1][k], w, acc1);
        acc2 = fmaf(sw[2][k], w, acc2);
        acc3 = fmaf(sw[3][k], w, acc3);
    }
    __syncthreads();
    sx[0][j] = gelu_exact(acc0 + bb);
    sx[1][j] = gelu_exact(acc1 + bb);
    sx[2][j] = gelu_exact(acc2 + bb);
    sx[3][j] = gelu_exact(acc3 + bb);
    __syncthreads();

    bb = b1[j];
    float r1 = rw[1];
    acc0 = acc1 = acc2 = acc3 = 0.f;
    for (int k = 0; k < 256; k++) {
        float w = W1[k * 256 + j];
        acc0 = fmaf(sx[0][k], w, acc0);
        acc1 = fmaf(sx[1][k], w, acc1);
        acc2 = fmaf(sx[2][k], w, acc2);
        acc3 = fmaf(sx[3][k], w, acc3);
    }
    sy[0][j] = gelu_exact(acc0 + bb) + r1 * sx[0][j];
    sy[1][j] = gelu_exact(acc1 + bb) + r1 * sx[1][j];
    sy[2][j] = gelu_exact(acc2 + bb) + r1 * sx[2][j];
    sy[3][j] = gelu_exact(acc3 + bb) + r1 * sx[3][j];
    __syncthreads();

    bb = b2[j];
    float r2 = rw[2];
    acc0 = acc1 = acc2 = acc3 = 0.f;
    for (int k = 0; k < 256; k++) {
        float w = W2[k * 256 + j];
        acc0 = fmaf(sy[0][k], w, acc0);
        acc1 = fmaf(sy[1][k], w, acc1);
        acc2 = fmaf(sy[2][k], w, acc2);
        acc3 = fmaf(sy[3][k], w, acc3);
    }
    {
        float z[4];
        z[0] = 0.1f * (gelu_exact(acc0 + bb) + r2 * sy[0][j]);
        z[1] = 0.1f * (gelu_exact(acc1 + bb) + r2 * sy[1][j]);
        z[2] = 0.1f * (gelu_exact(acc2 + bb) + r2 * sy[2][j]);
        z[3] = 0.1f * (gelu_exact(acc3 + bb) + r2 * sy[3][j]);
        #pragma unroll
        for (int i = 0; i < 4; i++)
            g_Ah[(size_t)(t0 + i) * KK + 192 + j] = __float2bfloat16(z[i]);
    }

    {
        int i = j >> 6, h = j & 63;
        float f  = sw[i][h];
        float ph = sw[i][128 + h];
        float sc = 0.0078125f * slamp[i];
        float sn, cs;
        sincosf(ph, &sn, &cs);
        size_t base = (size_t)(t0 + i) * KK;
        // freq: hi + lo (cross term needs the split)
        __nv_bfloat16 fh = __float2bfloat16(f);
        g_Ah[base + h] = fh;
        g_Al[(size_t)(t0 + i) * 64 + h] = __float2bfloat16(f - __bfloat162float(fh));
        // trig rows: hi only
        g_Ah[base + 64 + h]  = __float2bfloat16(cs * sc);
        g_Ah[base + 128 + h] = __float2bfloat16(sn * sc);
    }
}

// ---------------------------------------------------------------------------
// Vocab prep
// ---------------------------------------------------------------------------
__global__ void vocab_v2_kernel(const float* __restrict__ vf)
{
    int v = blockIdx.x * 256 + threadIdx.x;
    if (v >= NV) return;
    const float* r = vf + (size_t)v * NH;
    float s = 0.f;
    #pragma unroll
    for (int h = 0; h < NH; h++) s = fmaf(r[h], r[h], s);
    g_v2[v] = s;
}

// B rows [v][448]: cols [0,64)=vf (hi+lo), [64,128)=cos(vp) (hi), [128,192)=sin(vp) (hi)
__global__ void vocab_feat(const float* __restrict__ vf, const float* __restrict__ vp)
{
    size_t idx = (size_t)blockIdx.x * 256 + threadIdx.x;   // v*64 + h
    if (idx >= (size_t)NV * NH) return;
    int v = (int)(idx >> 6), h = (int)(idx & 63);
    float f = vf[idx];
    float p = vp[idx];
    float sn, cs;
    sincosf(p, &sn, &cs);
    size_t base = (size_t)v * KK;
    __nv_bfloat16 fh = __float2bfloat16(f);
    g_Bh[base + h] = fh;
    g_Bl[(size_t)v * 64 + h] = __float2bfloat16(f - __bfloat162float(fh));
    g_Bh[base + 64 + h]  = __float2bfloat16(cs);
    g_Bh[base + 128 + h] = __float2bfloat16(sn);
}

// B cols [192,448) = Wv^T (Wv is [256][32000]) via tiled transpose, hi only
__global__ void wv_transpose(const float* __restrict__ Wv)
{
    __shared__ float st[32][33];
    const int v0 = blockIdx.x * 32;
    const int k0 = blockIdx.y * 32;
    const int tx = threadIdx.x, ty = threadIdx.y;   // (32, 8)
    #pragma unroll
    for (int r = 0; r < 4; r++)
        st[ty + r * 8][tx] = Wv[(size_t)(k0 + ty + r * 8) * NV + v0 + tx];
    __syncthreads();
    #pragma unroll
    for (int r = 0; r < 4; r++) {
        int v = v0 + ty + r * 8, k = k0 + tx;
        g_Bh[(size_t)v * KK + 192 + k] = __float2bfloat16(st[tx][ty + r * 8]);
    }
}

// ---------------------------------------------------------------------------
// Main GEMM on mma.sync.m16n8k16.
// CTA 128x64, 8 warps (4M x 2N), warp tile 32x32 (R5 champion shape).
// Chunk 0 (cross, K [0,64)): bf16 3-product hi/lo split, then in-register
// transform  acc <- 0.1*bv - sqrt(max(f2+v2-2*acc,0))*lam.
// Chunks 1-6: single-product hi*hi (coherence*0.5*lam + 0.1*synthesis),
// accumulated on top — linear terms need no split.
// ---------------------------------------------------------------------------
__global__ void __launch_bounds__(256, 2)
spectral_hmma(const float* __restrict__ bv, float* __restrict__ out)
{
    extern __shared__ char smem[];
    const uint32_t sbase = smem_u32(smem);

    const int tid = threadIdx.x;
    const int wid = tid >> 5;
    const int lid = tid & 31;
    const int wm = wid & 3;          // 0..3 -> M offset wm*32
    const int wn = wid >> 2;         // 0..1 -> N offset wn*32
    const int v0 = blockIdx.x * CTA_N;
    const int m0 = blockIdx.y * CTA_M;

    // lane-derived ldmatrix address components
    const int a_row = lid & 15;
    const int a_c16 = (lid >> 4) & 1;
    const int b_row = ((lid >> 4) & 1) * 8 + (lid & 7);
    const int b_c16 = (lid >> 3) & 1;

    float acc[2][4][4];
    #pragma unroll
    for (int mt = 0; mt < 2; mt++)
        #pragma unroll
        for (int nt = 0; nt < 4; nt++)
            #pragma unroll
            for (int e = 0; e < 4; e++) acc[mt][nt][e] = 0.f;

    // hi-plane loader (A: 128 rows, B: 64 rows; 128B rows, SW128 swizzle)
    auto load_hi = [&](int stage, int kc) {
        const uint32_t sb = sbase + stage * STAGE_BYTES;
        #pragma unroll
        for (int i = 0; i < 4; i++) {
            int idx = tid + i * 256;
            int r = idx >> 3, u = idx & 7;
            uint32_t so = (uint32_t)(r * 128 + ((u * 16) ^ ((r & 7) << 4)));
            cpa16(sb + OFF_AH + so, g_Ah + (size_t)(m0 + r) * KK + kc + u * 8);
        }
        #pragma unroll
        for (int i = 0; i < 2; i++) {
            int idx = tid + i * 256;
            int r = idx >> 3, u = idx & 7;
            uint32_t so = (uint32_t)(r * 128 + ((u * 16) ^ ((r & 7) << 4)));
            cpa16(sb + OFF_BH + so, g_Bh + (size_t)(v0 + r) * KK + kc + u * 8);
        }
    };
    // lo planes (chunk 0 only; g_Al/g_Bl have row stride 64)
    auto load_lo0 = [&](int stage) {
        const uint32_t sb = sbase + stage * STAGE_BYTES;
        #pragma unroll
        for (int i = 0; i < 4; i++) {
            int idx = tid + i * 256;
            int r = idx >> 3, u = idx & 7;
            uint32_t so = (uint32_t)(r * 128 + ((u * 16) ^ ((r & 7) << 4)));
            cpa16(sb + OFF_AL + so, g_Al + (size_t)(m0 + r) * 64 + u * 8);
        }
        #pragma unroll
        for (int i = 0; i < 2; i++) {
            int idx = tid + i * 256;
            int r = idx >> 3, u = idx & 7;
            uint32_t so = (uint32_t)(r * 128 + ((u * 16) ^ ((r & 7) << 4)));
            cpa16(sb + OFF_BL + so, g_Bl + (size_t)(v0 + r) * 64 + u * 8);
        }
    };

    // prologue: chunk 0 (hi + lo) into stage 0
    load_hi(0, 0);
    load_lo0(0);
    CPA_COMMIT();

    #pragma unroll 1
    for (int c = 0; c < NCHUNK; c++) {
        if (c < NCHUNK - 1) {
            load_hi((c + 1) & 1, (c + 1) * KC);
            CPA_COMMIT();
            CPA_WAIT1();
        } else {
            CPA_WAIT0();
        }
        __syncthreads();

        const uint32_t sb = sbase + (c & 1) * STAGE_BYTES;

        if (c == 0) {
            // 3-product split chunk
            #pragma unroll
            for (int ks = 0; ks < 4; ks++) {
                uint32_t ah[2][4], al[2][4], bh[2][4], bl[2][4];
                #pragma unroll
                for (int mt = 0; mt < 2; mt++) {
                    int R = wm * 32 + mt * 16 + a_row;
                    uint32_t off = (uint32_t)(R * 128 + ((ks * 32 + a_c16 * 16) ^ ((R & 7) << 4)));
                    LDSM_X4(ah[mt], sb + OFF_AH + off);
                    LDSM_X4(al[mt], sb + OFF_AL + off);
                }
                #pragma unroll
                for (int ng = 0; ng < 2; ng++) {
                    int R = wn * 32 + ng * 16 + b_row;
                    uint32_t off = (uint32_t)(R * 128 + ((ks * 32 + b_c16 * 16) ^ ((R & 7) << 4)));
                    LDSM_X4(bh[ng], sb + OFF_BH + off);
                    LDSM_X4(bl[ng], sb + OFF_BL + off);
                }
                #pragma unroll
                for (int mt = 0; mt < 2; mt++)
                    #pragma unroll
                    for (int nt = 0; nt < 4; nt++) {
                        int ng = nt >> 1, sub = nt & 1;
                        MMA16816(acc[mt][nt], ah[mt], bh[ng][sub * 2], bh[ng][sub * 2 + 1]);
                        MMA16816(acc[mt][nt], ah[mt], bl[ng][sub * 2], bl[ng][sub * 2 + 1]);
                        MMA16816(acc[mt][nt], al[mt], bh[ng][sub * 2], bh[ng][sub * 2 + 1]);
                    }
            }
            // transform: acc <- 0.1*bv - sqrt(max(f2+v2-2*acc,0))*lam
            #pragma unroll
            for (int mt = 0; mt < 2; mt++) {
                int r0 = m0 + wm * 32 + mt * 16 + (lid >> 2);
                int r1 = r0 + 8;
                float f2a = g_f2[r0],  lma = g_lamp[r0];
                float f2b = g_f2[r1],  lmb = g_lamp[r1];
                #pragma unroll
                for (int nt = 0; nt < 4; nt++) {
                    int c0 = v0 + wn * 32 + (nt >> 1) * 16 + (nt & 1) * 8 + 2 * (lid & 3);
                    float v2x = g_v2[c0],     bvx = 0.1f * bv[c0];
                    float v2y = g_v2[c0 + 1], bvy = 0.1f * bv[c0 + 1];
                    float* a = acc[mt][nt];
                    a[0] = bvx - sqrtf(fmaxf(f2a + v2x - 2.f * a[0], 0.f)) * lma;
                    a[1] = bvy - sqrtf(fmaxf(f2a + v2y - 2.f * a[1], 0.f)) * lma;
                    a[2] = bvx - sqrtf(fmaxf(f2b + v2x - 2.f * a[2], 0.f)) * lmb;
                    a[3] = bvy - sqrtf(fmaxf(f2b + v2y - 2.f * a[3], 0.f)) * lmb;
                }
            }
        } else {
            // single-product hi*hi chunks
            #pragma unroll
            for (int ks = 0; ks < 4; ks++) {
                uint32_t ah[2][4], bh[2][4];
                #pragma unroll
                for (int mt = 0; mt < 2; mt++) {
                    int R = wm * 32 + mt * 16 + a_row;
                    uint32_t off = (uint32_t)(R * 128 + ((ks * 32 + a_c16 * 16) ^ ((R & 7) << 4)));
                    LDSM_X4(ah[mt], sb + OFF_AH + off);
                }
                #pragma unroll
                for (int ng = 0; ng < 2; ng++) {
                    int R = wn * 32 + ng * 16 + b_row;
                    uint32_t off = (uint32_t)(R * 128 + ((ks * 32 + b_c16 * 16) ^ ((R & 7) << 4)));
                    LDSM_X4(bh[ng], sb + OFF_BH + off);
                }
                #pragma unroll
                for (int mt = 0; mt < 2; mt++)
                    #pragma unroll
                    for (int nt = 0; nt < 4; nt++) {
                        int ng = nt >> 1, sub = nt & 1;
                        MMA16816(acc[mt][nt], ah[mt], bh[ng][sub * 2], bh[ng][sub * 2 + 1]);
                    }
            }
        }
        __syncthreads();
    }

    // Writeout
    #pragma unroll
    for (int mt = 0; mt < 2; mt++) {
        size_t r0 = (size_t)(m0 + wm * 32 + mt * 16 + (lid >> 2));
        #pragma unroll
        for (int nt = 0; nt < 4; nt++) {
            int c0 = v0 + wn * 32 + (nt >> 1) * 16 + (nt & 1) * 8 + 2 * (lid & 3);
            float2 lo = make_float2(acc[mt][nt][0], acc[mt][nt][1]);
            float2 hi = make_float2(acc[mt][nt][2], acc[mt][nt][3]);
            *(float2*)(out + r0 * NV + c0)       = lo;
            *(float2*)(out + (r0 + 8) * NV + c0) = hi;
        }
    }
}

// ---------------------------------------------------------------------------
extern "C" void kernel_launch(void* const* d_in, const int* in_sizes, int n_in,
                              void* d_out, int out_size)
{
    const float* wave = (const float*)d_in[0];   // (2,1024,192)
    const float* vf   = (const float*)d_in[1];   // (32000,64)
    const float* vp   = (const float*)d_in[2];   // (32000,64)
    const float* W0   = (const float*)d_in[3];   // (192,256)
    const float* b0   = (const float*)d_in[4];
    const float* W1   = (const float*)d_in[5];   // (256,256)
    const float* b1   = (const float*)d_in[6];
    const float* W2   = (const float*)d_in[7];   // (256,256)
    const float* b2   = (const float*)d_in[8];
    const float* Wv   = (const float*)d_in[9];   // (256,32000)
    const float* bv   = (const float*)d_in[10];  // (32000,)
    const float* rw   = (const float*)d_in[11];  // (3,)
    float* out = (float*)d_out;

    cudaFuncSetAttribute(spectral_hmma,
                         cudaFuncAttributeMaxDynamicSharedMemorySize, SMEM_TOTAL);

    token_prep<<<NT / 4, 256>>>(wave, W0, b0, W1, b1, W2, b2, rw);
    vocab_v2_kernel<<<(NV + 255) / 256, 256>>>(vf);
    vocab_feat<<<(int)(((size_t)NV * NH + 255) / 256), 256>>>(vf, vp);
    wv_transpose<<<dim3(NV / 32, 256 / 32), dim3(32, 8)>>>(Wv);
    spectral_hmma<<<dim3(NV / CTA_N, NT / CTA_M), 256, SMEM_TOTAL>>>(bv, out);
}

// round 11
// speedup vs baseline: 1.7863x; 1.0443x over previous
#include <cuda_runtime.h>
#include <cuda_bf16.h>
#include <math.h>
#include <stdint.h>

// ---------------------------------------------------------------------------
// Problem constants
// ---------------------------------------------------------------------------
static constexpr int NT = 2048;      // tokens (B*L)
static constexpr int NH = 64;
static constexpr int NV = 32000;
static constexpr int KK = 448;       // 64 freq + 64 cos + 64 sin + 256 hidden

// GEMM tiling
static constexpr int CTA_M = 128;
static constexpr int CTA_N = 128;
static constexpr int KC    = 64;               // K per chunk
static constexpr int NCHUNK = KK / KC;         // 7

// SMEM layout (bytes). Rows are 128B (64 bf16), SW128-swizzled.
// Two 32KB hi stages (AH+BH) + one 32KB one-shot lo region (AL+BL, chunk 0).
static constexpr int AH_BYTES = CTA_M * KC * 2;   // 16384
static constexpr int BH_BYTES = CTA_N * KC * 2;   // 16384
static constexpr int STAGE_BYTES = AH_BYTES + BH_BYTES;          // 32768
static constexpr int OFF_BH  = AH_BYTES;                          // within stage
static constexpr int OFF_LO  = 2 * STAGE_BYTES;                   // 65536
static constexpr int OFF_AL  = OFF_LO;
static constexpr int OFF_BL  = OFF_LO + AH_BYTES;                 // 81920
static constexpr int SMEM_TOTAL = 3 * STAGE_BYTES;                // 98304 -> 2 CTAs/SM

// ---------------------------------------------------------------------------
// Device scratch (allocation-free).  lo planes exist only for K in [0,64).
// ---------------------------------------------------------------------------
__device__ __nv_bfloat16 g_Ah[NT * KK];
__device__ __nv_bfloat16 g_Al[NT * 64];
__device__ __nv_bfloat16 g_Bh[(size_t)NV * KK];
__device__ __nv_bfloat16 g_Bl[(size_t)NV * 64];
__device__ float g_v2[NV];
__device__ float g_f2[NT];
__device__ float g_lamp[NT];

// ---------------------------------------------------------------------------
// Helpers
// ---------------------------------------------------------------------------
__device__ __forceinline__ uint32_t smem_u32(const void* p) {
    uint32_t a;
    asm("{ .reg .u64 t; cvta.to.shared.u64 t, %1; cvt.u32.u64 %0, t; }" : "=r"(a) : "l"(p));
    return a;
}

__device__ __forceinline__ void cpa16(uint32_t saddr, const void* gaddr) {
    asm volatile("cp.async.cg.shared.global [%0], [%1], 16;" :: "r"(saddr), "l"(gaddr));
}
#define CPA_COMMIT() asm volatile("cp.async.commit_group;" ::: "memory")
#define CPA_WAIT1()  asm volatile("cp.async.wait_group 1;" ::: "memory")
#define CPA_WAIT0()  asm volatile("cp.async.wait_group 0;" ::: "memory")

#define LDSM_X4(r, addr) \
    asm volatile("ldmatrix.sync.aligned.m8n8.x4.shared.b16 {%0,%1,%2,%3}, [%4];" \
        : "=r"((r)[0]), "=r"((r)[1]), "=r"((r)[2]), "=r"((r)[3]) : "r"(addr))

#define MMA16816(C, A, B0, B1) \
    asm volatile("mma.sync.aligned.m16n8k16.row.col.f32.bf16.bf16.f32 " \
        "{%0,%1,%2,%3}, {%4,%5,%6,%7}, {%8,%9}, {%0,%1,%2,%3};" \
        : "+f"((C)[0]), "+f"((C)[1]), "+f"((C)[2]), "+f"((C)[3]) \
        : "r"((A)[0]), "r"((A)[1]), "r"((A)[2]), "r"((A)[3]), "r"(B0), "r"(B1))

__device__ __forceinline__ float gelu_exact(float x) {
    return 0.5f * x * (1.0f + erff(x * 0.7071067811865476f));
}

// ---------------------------------------------------------------------------
// Token prep: 4 tokens / block, 256 threads.  Writes A rows [t][448]:
//   cols [0,64)=freq (hi + lo), [64,128)=cos(ph)*sc (hi), [128,192)=sin(ph)*sc (hi),
//   [192,448)=0.1*x (hi).   sc = (0.5/64) * log1p(sum amps)
// ---------------------------------------------------------------------------
__global__ void token_prep(const float* __restrict__ wave,
                           const float* __restrict__ W0, const float* __restrict__ b0,
                           const float* __restrict__ W1, const float* __restrict__ b1,
                           const float* __restrict__ W2, const float* __restrict__ b2,
                           const float* __restrict__ rw)
{
    __shared__ float sw[4][192];
    __shared__ float sx[4][256];
    __shared__ float sy[4][256];
    __shared__ float slamp[4];

    const int t0 = blockIdx.x * 4;
    const int j  = threadIdx.x;

    for (int i = j; i < 4 * 192; i += 256) {
        int tok = i / 192, kk = i % 192;
        sw[tok][kk] = wave[(size_t)(t0 + tok) * 192 + kk];
    }
    __syncthreads();

    if (j < 8) {
        int tok = j & 3;
        if (j < 4) {
            float s = 0.f;
            for (int h = 0; h < NH; h++) { float f = sw[tok][h]; s += f * f; }
            g_f2[t0 + tok] = s;
        } else {
            float s = 0.f;
            for (int h = 0; h < NH; h++) s += sw[tok][64 + h];
            float l = log1pf(s);
            slamp[tok] = l;
            g_lamp[t0 + tok] = l;
        }
    }

    // layer 0: 192 -> 256
    float acc0 = 0.f, acc1 = 0.f, acc2 = 0.f, acc3 = 0.f;
    float bb = b0[j];
    for (int k = 0; k < 192; k++) {
        float w = W0[k * 256 + j];
        acc0 = fmaf(sw[0][k], w, acc0);
        acc1 = fmaf(sw[1][k], w, acc1);
        acc2 = fmaf(sw[2][k], w, acc2);
        acc3 = fmaf(sw[3][k], w, acc3);
    }
    __syncthreads();
    sx[0][j] = gelu_exact(acc0 + bb);
    sx[1][j] = gelu_exact(acc1 + bb);
    sx[2][j] = gelu_exact(acc2 + bb);
    sx[3][j] = gelu_exact(acc3 + bb);
    __syncthreads();

    bb = b1[j];
    float r1 = rw[1];
    acc0 = acc1 = acc2 = acc3 = 0.f;
    for (int k = 0; k < 256; k++) {
        float w = W1[k * 256 + j];
        acc0 = fmaf(sx[0][k], w, acc0);
        acc1 = fmaf(sx[1][k], w, acc1);
        acc2 = fmaf(sx[2][k], w, acc2);
        acc3 = fmaf(sx[3][k], w, acc3);
    }
    sy[0][j] = gelu_exact(acc0 + bb) + r1 * sx[0][j];
    sy[1][j] = gelu_exact(acc1 + bb) + r1 * sx[1][j];
    sy[2][j] = gelu_exact(acc2 + bb) + r1 * sx[2][j];
    sy[3][j] = gelu_exact(acc3 + bb) + r1 * sx[3][j];
    __syncthreads();

    bb = b2[j];
    float r2 = rw[2];
    acc0 = acc1 = acc2 = acc3 = 0.f;
    for (int k = 0; k < 256; k++) {
        float w = W2[k * 256 + j];
        acc0 = fmaf(sy[0][k], w, acc0);
        acc1 = fmaf(sy[1][k], w, acc1);
        acc2 = fmaf(sy[2][k], w, acc2);
        acc3 = fmaf(sy[3][k], w, acc3);
    }
    {
        float z[4];
        z[0] = 0.1f * (gelu_exact(acc0 + bb) + r2 * sy[0][j]);
        z[1] = 0.1f * (gelu_exact(acc1 + bb) + r2 * sy[1][j]);
        z[2] = 0.1f * (gelu_exact(acc2 + bb) + r2 * sy[2][j]);
        z[3] = 0.1f * (gelu_exact(acc3 + bb) + r2 * sy[3][j]);
        #pragma unroll
        for (int i = 0; i < 4; i++)
            g_Ah[(size_t)(t0 + i) * KK + 192 + j] = __float2bfloat16(z[i]);
    }

    {
        int i = j >> 6, h = j & 63;
        float f  = sw[i][h];
        float ph = sw[i][128 + h];
        float sc = 0.0078125f * slamp[i];
        float sn, cs;
        sincosf(ph, &sn, &cs);
        size_t base = (size_t)(t0 + i) * KK;
        __nv_bfloat16 fh = __float2bfloat16(f);
        g_Ah[base + h] = fh;
        g_Al[(size_t)(t0 + i) * 64 + h] = __float2bfloat16(f - __bfloat162float(fh));
        g_Ah[base + 64 + h]  = __float2bfloat16(cs * sc);
        g_Ah[base + 128 + h] = __float2bfloat16(sn * sc);
    }
}

// ---------------------------------------------------------------------------
// Vocab prep
// ---------------------------------------------------------------------------
__global__ void vocab_v2_kernel(const float* __restrict__ vf)
{
    int v = blockIdx.x * 256 + threadIdx.x;
    if (v >= NV) return;
    const float* r = vf + (size_t)v * NH;
    float s = 0.f;
    #pragma unroll
    for (int h = 0; h < NH; h++) s = fmaf(r[h], r[h], s);
    g_v2[v] = s;
}

// B rows [v][448]: cols [0,64)=vf (hi+lo), [64,128)=cos(vp) (hi), [128,192)=sin(vp) (hi)
__global__ void vocab_feat(const float* __restrict__ vf, const float* __restrict__ vp)
{
    size_t idx = (size_t)blockIdx.x * 256 + threadIdx.x;   // v*64 + h
    if (idx >= (size_t)NV * NH) return;
    int v = (int)(idx >> 6), h = (int)(idx & 63);
    float f = vf[idx];
    float p = vp[idx];
    float sn, cs;
    sincosf(p, &sn, &cs);
    size_t base = (size_t)v * KK;
    __nv_bfloat16 fh = __float2bfloat16(f);
    g_Bh[base + h] = fh;
    g_Bl[(size_t)v * 64 + h] = __float2bfloat16(f - __bfloat162float(fh));
    g_Bh[base + 64 + h]  = __float2bfloat16(cs);
    g_Bh[base + 128 + h] = __float2bfloat16(sn);
}

// B cols [192,448) = Wv^T (Wv is [256][32000]) via tiled transpose, hi only
__global__ void wv_transpose(const float* __restrict__ Wv)
{
    __shared__ float st[32][33];
    const int v0 = blockIdx.x * 32;
    const int k0 = blockIdx.y * 32;
    const int tx = threadIdx.x, ty = threadIdx.y;   // (32, 8)
    #pragma unroll
    for (int r = 0; r < 4; r++)
        st[ty + r * 8][tx] = Wv[(size_t)(k0 + ty + r * 8) * NV + v0 + tx];
    __syncthreads();
    #pragma unroll
    for (int r = 0; r < 4; r++) {
        int v = v0 + ty + r * 8, k = k0 + tx;
        g_Bh[(size_t)v * KK + 192 + k] = __float2bfloat16(st[tx][ty + r * 8]);
    }
}

// ---------------------------------------------------------------------------
// Main GEMM on mma.sync.m16n8k16.
// CTA 128x128, 8 warps (2M x 4N), warp tile 64x32, 96KB smem -> 2 CTAs/SM.
// Chunk 0 (cross, K [0,64)): 3-product hi/lo split using the one-shot lo
// region, then in-register transform acc <- 0.1*bv - sqrt(...)*lam.
// Chunks 1-6: single-product hi*hi accumulated on top.
// ---------------------------------------------------------------------------
__global__ void __launch_bounds__(256, 2)
spectral_hmma(const float* __restrict__ bv, float* __restrict__ out)
{
    extern __shared__ char smem[];
    const uint32_t sbase = smem_u32(smem);

    const int tid = threadIdx.x;
    const int wid = tid >> 5;
    const int lid = tid & 31;
    const int wm = wid & 1;          // M offset wm*64
    const int wn = wid >> 1;         // 0..3 -> N offset wn*32
    const int v0 = blockIdx.x * CTA_N;
    const int m0 = blockIdx.y * CTA_M;

    // lane-derived ldmatrix address components
    const int a_row = lid & 15;
    const int a_c16 = (lid >> 4) & 1;
    const int b_row = ((lid >> 4) & 1) * 8 + (lid & 7);
    const int b_c16 = (lid >> 3) & 1;

    float acc[4][4][4];
    #pragma unroll
    for (int mt = 0; mt < 4; mt++)
        #pragma unroll
        for (int nt = 0; nt < 4; nt++)
            #pragma unroll
            for (int e = 0; e < 4; e++) acc[mt][nt][e] = 0.f;

    // hi-plane loader: A 128 rows + B 128 rows (128B rows, SW128)
    auto load_hi = [&](int stage, int kc) {
        const uint32_t sb = sbase + stage * STAGE_BYTES;
        #pragma unroll
        for (int i = 0; i < 4; i++) {
            int idx = tid + i * 256;
            int r = idx >> 3, u = idx & 7;
            uint32_t so = (uint32_t)(r * 128 + ((u * 16) ^ ((r & 7) << 4)));
            cpa16(sb + so, g_Ah + (size_t)(m0 + r) * KK + kc + u * 8);
        }
        #pragma unroll
        for (int i = 0; i < 4; i++) {
            int idx = tid + i * 256;
            int r = idx >> 3, u = idx & 7;
            uint32_t so = (uint32_t)(r * 128 + ((u * 16) ^ ((r & 7) << 4)));
            cpa16(sb + OFF_BH + so, g_Bh + (size_t)(v0 + r) * KK + kc + u * 8);
        }
    };
    // lo planes (one-shot, chunk 0; g_Al/g_Bl row stride 64)
    auto load_lo = [&]() {
        #pragma unroll
        for (int i = 0; i < 4; i++) {
            int idx = tid + i * 256;
            int r = idx >> 3, u = idx & 7;
            uint32_t so = (uint32_t)(r * 128 + ((u * 16) ^ ((r & 7) << 4)));
            cpa16(sbase + OFF_AL + so, g_Al + (size_t)(m0 + r) * 64 + u * 8);
        }
        #pragma unroll
        for (int i = 0; i < 4; i++) {
            int idx = tid + i * 256;
            int r = idx >> 3, u = idx & 7;
            uint32_t so = (uint32_t)(r * 128 + ((u * 16) ^ ((r & 7) << 4)));
            cpa16(sbase + OFF_BL + so, g_Bl + (size_t)(v0 + r) * 64 + u * 8);
        }
    };

    // prologue: chunk 0 hi + lo as one group
    load_hi(0, 0);
    load_lo();
    CPA_COMMIT();

    #pragma unroll 1
    for (int c = 0; c < NCHUNK; c++) {
        if (c < NCHUNK - 1) {
            load_hi((c + 1) & 1, (c + 1) * KC);
            CPA_COMMIT();
            CPA_WAIT1();
        } else {
            CPA_WAIT0();
        }
        __syncthreads();

        const uint32_t sb = sbase + (c & 1) * STAGE_BYTES;

        if (c == 0) {
            // 3-product split chunk (hi from stage 0, lo from one-shot region)
            #pragma unroll
            for (int ks = 0; ks < 4; ks++) {
                uint32_t ah[4][4], al[4][4], bh[2][4], bl[2][4];
                #pragma unroll
                for (int mt = 0; mt < 4; mt++) {
                    int R = wm * 64 + mt * 16 + a_row;
                    uint32_t kpat = (uint32_t)((ks * 32 + a_c16 * 16) ^ ((R & 7) << 4));
                    LDSM_X4(ah[mt], sb + (uint32_t)(R * 128) + kpat);
                    LDSM_X4(al[mt], sbase + OFF_AL + (uint32_t)(R * 128) + kpat);
                }
                #pragma unroll
                for (int ng = 0; ng < 2; ng++) {
                    int R = wn * 32 + ng * 16 + b_row;
                    uint32_t kpat = (uint32_t)((ks * 32 + b_c16 * 16) ^ ((R & 7) << 4));
                    LDSM_X4(bh[ng], sb + OFF_BH + (uint32_t)(R * 128) + kpat);
                    LDSM_X4(bl[ng], sbase + OFF_BL + (uint32_t)(R * 128) + kpat);
                }
                #pragma unroll
                for (int mt = 0; mt < 4; mt++)
                    #pragma unroll
                    for (int nt = 0; nt < 4; nt++) {
                        int ng = nt >> 1, sub = nt & 1;
                        MMA16816(acc[mt][nt], ah[mt], bh[ng][sub * 2], bh[ng][sub * 2 + 1]);
                        MMA16816(acc[mt][nt], ah[mt], bl[ng][sub * 2], bl[ng][sub * 2 + 1]);
                        MMA16816(acc[mt][nt], al[mt], bh[ng][sub * 2], bh[ng][sub * 2 + 1]);
                    }
            }
            // transform: acc <- 0.1*bv - sqrt(max(f2+v2-2*acc,0))*lam
            #pragma unroll
            for (int mt = 0; mt < 4; mt++) {
                int r0 = m0 + wm * 64 + mt * 16 + (lid >> 2);
                int r1 = r0 + 8;
                float f2a = g_f2[r0],  lma = g_lamp[r0];
                float f2b = g_f2[r1],  lmb = g_lamp[r1];
                #pragma unroll
                for (int nt = 0; nt < 4; nt++) {
                    int c0 = v0 + wn * 32 + (nt >> 1) * 16 + (nt & 1) * 8 + 2 * (lid & 3);
                    float v2x = g_v2[c0],     bvx = 0.1f * bv[c0];
                    float v2y = g_v2[c0 + 1], bvy = 0.1f * bv[c0 + 1];
                    float* a = acc[mt][nt];
                    a[0] = bvx - sqrtf(fmaxf(f2a + v2x - 2.f * a[0], 0.f)) * lma;
                    a[1] = bvy - sqrtf(fmaxf(f2a + v2y - 2.f * a[1], 0.f)) * lma;
                    a[2] = bvx - sqrtf(fmaxf(f2b + v2x - 2.f * a[2], 0.f)) * lmb;
                    a[3] = bvy - sqrtf(fmaxf(f2b + v2y - 2.f * a[3], 0.f)) * lmb;
                }
            }
        } else {
            // single-product hi*hi chunks
            #pragma unroll
            for (int ks = 0; ks < 4; ks++) {
                uint32_t ah[4][4], bh[2][4];
                #pragma unroll
                for (int mt = 0; mt < 4; mt++) {
                    int R = wm * 64 + mt * 16 + a_row;
                    uint32_t off = (uint32_t)(R * 128 + ((ks * 32 + a_c16 * 16) ^ ((R & 7) << 4)));
                    LDSM_X4(ah[mt], sb + off);
                }
                #pragma unroll
                for (int ng = 0; ng < 2; ng++) {
                    int R = wn * 32 + ng * 16 + b_row;
                    uint32_t off = (uint32_t)(R * 128 + ((ks * 32 + b_c16 * 16) ^ ((R & 7) << 4)));
                    LDSM_X4(bh[ng], sb + OFF_BH + off);
                }
                #pragma unroll
                for (int mt = 0; mt < 4; mt++)
                    #pragma unroll
                    for (int nt = 0; nt < 4; nt++) {
                        int ng = nt >> 1, sub = nt & 1;
                        MMA16816(acc[mt][nt], ah[mt], bh[ng][sub * 2], bh[ng][sub * 2 + 1]);
                    }
            }
        }
        __syncthreads();
    }

    // Writeout
    #pragma unroll
    for (int mt = 0; mt < 4; mt++) {
        size_t r0 = (size_t)(m0 + wm * 64 + mt * 16 + (lid >> 2));
        #pragma unroll
        for (int nt = 0; nt < 4; nt++) {
            int c0 = v0 + wn * 32 + (nt >> 1) * 16 + (nt & 1) * 8 + 2 * (lid & 3);
            float2 lo = make_float2(acc[mt][nt][0], acc[mt][nt][1]);
            float2 hi = make_float2(acc[mt][nt][2], acc[mt][nt][3]);
            *(float2*)(out + r0 * NV + c0)       = lo;
            *(float2*)(out + (r0 + 8) * NV + c0) = hi;
        }
    }
}

// ---------------------------------------------------------------------------
extern "C" void kernel_launch(void* const* d_in, const int* in_sizes, int n_in,
                              void* d_out, int out_size)
{
    const float* wave = (const float*)d_in[0];   // (2,1024,192)
    const float* vf   = (const float*)d_in[1];   // (32000,64)
    const float* vp   = (const float*)d_in[2];   // (32000,64)
    const float* W0   = (const float*)d_in[3];   // (192,256)
    const float* b0   = (const float*)d_in[4];
    const float* W1   = (const float*)d_in[5];   // (256,256)
    const float* b1   = (const float*)d_in[6];
    const float* W2   = (const float*)d_in[7];   // (256,256)
    const float* b2   = (const float*)d_in[8];
    const float* Wv   = (const float*)d_in[9];   // (256,32000)
    const float* bv   = (const float*)d_in[10];  // (32000,)
    const float* rw   = (const float*)d_in[11];  // (3,)
    float* out = (float*)d_out;

    cudaFuncSetAttribute(spectral_hmma,
                         cudaFuncAttributeMaxDynamicSharedMemorySize, SMEM_TOTAL);

    token_prep<<<NT / 4, 256>>>(wave, W0, b0, W1, b1, W2, b2, rw);
    vocab_v2_kernel<<<(NV + 255) / 256, 256>>>(vf);
    vocab_feat<<<(int)(((size_t)NV * NH + 255) / 256), 256>>>(vf, vp);
    wv_transpose<<<dim3(NV / 32, 256 / 32), dim3(32, 8)>>>(Wv);
    spectral_hmma<<<dim3(NV / CTA_N, NT / CTA_M), 256, SMEM_TOTAL>>>(bv, out);
}

// round 13
// speedup vs baseline: 1.8879x; 1.0569x over previous
#include <cuda_runtime.h>
#include <cuda_bf16.h>
#include <math.h>
#include <stdint.h>

// ---------------------------------------------------------------------------
// Problem constants
// ---------------------------------------------------------------------------
static constexpr int NT = 2048;      // tokens (B*L)
static constexpr int NH = 64;
static constexpr int NV = 32000;
static constexpr int KK = 448;       // 64 freq + 64 cos + 64 sin + 256 hidden

// GEMM tiling
static constexpr int CTA_M = 128;
static constexpr int CTA_N = 128;
static constexpr int KC    = 64;               // K per chunk
static constexpr int NCHUNK = KK / KC;         // 7

// SMEM layout (bytes). Rows are 128B (64 bf16), SW128-swizzled.
// Two 32KB hi stages + one 32KB region that is the chunk-0 lo planes AND,
// after chunk 0 is consumed, the third rotating hi stage (lo-overlay).
static constexpr int AH_BYTES = CTA_M * KC * 2;   // 16384
static constexpr int BH_BYTES = CTA_N * KC * 2;   // 16384
static constexpr int STAGE_BYTES = AH_BYTES + BH_BYTES;          // 32768
static constexpr int OFF_BH  = AH_BYTES;                          // within stage
static constexpr int OFF_AL  = 2 * STAGE_BYTES;                   // 65536
static constexpr int OFF_BL  = 2 * STAGE_BYTES + AH_BYTES;        // 81920
static constexpr int SMEM_TOTAL = 3 * STAGE_BYTES;                // 98304 -> 2 CTAs/SM

// ---------------------------------------------------------------------------
// Device scratch (allocation-free).  lo planes exist only for K in [0,64).
// ---------------------------------------------------------------------------
__device__ __nv_bfloat16 g_Ah[NT * KK];
__device__ __nv_bfloat16 g_Al[NT * 64];
__device__ __nv_bfloat16 g_Bh[(size_t)NV * KK];
__device__ __nv_bfloat16 g_Bl[(size_t)NV * 64];
__device__ float g_v2[NV];
__device__ float g_f2[NT];
__device__ float g_lamp[NT];

// ---------------------------------------------------------------------------
// Helpers
// ---------------------------------------------------------------------------
__device__ __forceinline__ uint32_t smem_u32(const void* p) {
    uint32_t a;
    asm("{ .reg .u64 t; cvta.to.shared.u64 t, %1; cvt.u32.u64 %0, t; }" : "=r"(a) : "l"(p));
    return a;
}

__device__ __forceinline__ void cpa16(uint32_t saddr, const void* gaddr) {
    asm volatile("cp.async.cg.shared.global [%0], [%1], 16;" :: "r"(saddr), "l"(gaddr));
}
#define CPA_COMMIT() asm volatile("cp.async.commit_group;" ::: "memory")
#define CPA_WAIT1()  asm volatile("cp.async.wait_group 1;" ::: "memory")
#define CPA_WAIT0()  asm volatile("cp.async.wait_group 0;" ::: "memory")

#define LDSM_X4(r, addr) \
    asm volatile("ldmatrix.sync.aligned.m8n8.x4.shared.b16 {%0,%1,%2,%3}, [%4];" \
        : "=r"((r)[0]), "=r"((r)[1]), "=r"((r)[2]), "=r"((r)[3]) : "r"(addr))

#define MMA16816(C, A, B0, B1) \
    asm volatile("mma.sync.aligned.m16n8k16.row.col.f32.bf16.bf16.f32 " \
        "{%0,%1,%2,%3}, {%4,%5,%6,%7}, {%8,%9}, {%0,%1,%2,%3};" \
        : "+f"((C)[0]), "+f"((C)[1]), "+f"((C)[2]), "+f"((C)[3]) \
        : "r"((A)[0]), "r"((A)[1]), "r"((A)[2]), "r"((A)[3]), "r"(B0), "r"(B1))

__device__ __forceinline__ float gelu_exact(float x) {
    return 0.5f * x * (1.0f + erff(x * 0.7071067811865476f));
}

// ---------------------------------------------------------------------------
// Token prep: 4 tokens / block, 256 threads.  Writes A rows [t][448]:
//   cols [0,64)=freq (hi + lo), [64,128)=cos(ph)*sc (hi), [128,192)=sin(ph)*sc (hi),
//   [192,448)=0.1*x (hi).   sc = (0.5/64) * log1p(sum amps)
// ---------------------------------------------------------------------------
__global__ void token_prep(const float* __restrict__ wave,
                           const float* __restrict__ W0, const float* __restrict__ b0,
                           const float* __restrict__ W1, const float* __restrict__ b1,
                           const float* __restrict__ W2, const float* __restrict__ b2,
                           const float* __restrict__ rw)
{
    __shared__ float sw[4][192];
    __shared__ float sx[4][256];
    __shared__ float sy[4][256];
    __shared__ float slamp[4];

    const int t0 = blockIdx.x * 4;
    const int j  = threadIdx.x;

    for (int i = j; i < 4 * 192; i += 256) {
        int tok = i / 192, kk = i % 192;
        sw[tok][kk] = wave[(size_t)(t0 + tok) * 192 + kk];
    }
    __syncthreads();

    if (j < 8) {
        int tok = j & 3;
        if (j < 4) {
            float s = 0.f;
            for (int h = 0; h < NH; h++) { float f = sw[tok][h]; s += f * f; }
            g_f2[t0 + tok] = s;
        } else {
            float s = 0.f;
            for (int h = 0; h < NH; h++) s += sw[tok][64 + h];
            float l = log1pf(s);
            slamp[tok] = l;
            g_lamp[t0 + tok] = l;
        }
    }

    // layer 0: 192 -> 256
    float acc0 = 0.f, acc1 = 0.f, acc2 = 0.f, acc3 = 0.f;
    float bb = b0[j];
    for (int k = 0; k < 192; k++) {
        float w = W0[k * 256 + j];
        acc0 = fmaf(sw[0][k], w, acc0);
        acc1 = fmaf(sw[1][k], w, acc1);
        acc2 = fmaf(sw[2][k], w, acc2);
        acc3 = fmaf(sw[3][k], w, acc3);
    }
    __syncthreads();
    sx[0][j] = gelu_exact(acc0 + bb);
    sx[1][j] = gelu_exact(acc1 + bb);
    sx[2][j] = gelu_exact(acc2 + bb);
    sx[3][j] = gelu_exact(acc3 + bb);
    __syncthreads();

    bb = b1[j];
    float r1 = rw[1];
    acc0 = acc1 = acc2 = acc3 = 0.f;
    for (int k = 0; k < 256; k++) {
        float w = W1[k * 256 + j];
        acc0 = fmaf(sx[0][k], w, acc0);
        acc1 = fmaf(sx[1][k], w, acc1);
        acc2 = fmaf(sx[2][k], w, acc2);
        acc3 = fmaf(sx[3][k], w, acc3);
    }
    sy[0][j] = gelu_exact(acc0 + bb) + r1 * sx[0][j];
    sy[1][j] = gelu_exact(acc1 + bb) + r1 * sx[1][j];
    sy[2][j] = gelu_exact(acc2 + bb) + r1 * sx[2][j];
    sy[3][j] = gelu_exact(acc3 + bb) + r1 * sx[3][j];
    __syncthreads();

    bb = b2[j];
    float r2 = rw[2];
    acc0 = acc1 = acc2 = acc3 = 0.f;
    for (int k = 0; k < 256; k++) {
        float w = W2[k * 256 + j];
        acc0 = fmaf(sy[0][k], w, acc0);
        acc1 = fmaf(sy[1][k], w, acc1);
        acc2 = fmaf(sy[2][k], w, acc2);
        acc3 = fmaf(sy[3][k], w, acc3);
    }
    {
        float z[4];
        z[0] = 0.1f * (gelu_exact(acc0 + bb) + r2 * sy[0][j]);
        z[1] = 0.1f * (gelu_exact(acc1 + bb) + r2 * sy[1][j]);
        z[2] = 0.1f * (gelu_exact(acc2 + bb) + r2 * sy[2][j]);
        z[3] = 0.1f * (gelu_exact(acc3 + bb) + r2 * sy[3][j]);
        #pragma unroll
        for (int i = 0; i < 4; i++)
            g_Ah[(size_t)(t0 + i) * KK + 192 + j] = __float2bfloat16(z[i]);
    }

    {
        int i = j >> 6, h = j & 63;
        float f  = sw[i][h];
        float ph = sw[i][128 + h];
        float sc = 0.0078125f * slamp[i];
        float sn, cs;
        sincosf(ph, &sn, &cs);
        size_t base = (size_t)(t0 + i) * KK;
        __nv_bfloat16 fh = __float2bfloat16(f);
        g_Ah[base + h] = fh;
        g_Al[(size_t)(t0 + i) * 64 + h] = __float2bfloat16(f - __bfloat162float(fh));
        g_Ah[base + 64 + h]  = __float2bfloat16(cs * sc);
        g_Ah[base + 128 + h] = __float2bfloat16(sn * sc);
    }
}

// ---------------------------------------------------------------------------
// Vocab prep: 8 threads per vocab row.  float4 loads, 16B packed bf16 stores,
// v2 folded in via 8-lane shfl reduction.
// B rows [v][448]: cols [0,64)=vf (hi+lo), [64,128)=cos(vp), [128,192)=sin(vp)
// ---------------------------------------------------------------------------
__global__ void vocab_feat(const float* __restrict__ vf, const float* __restrict__ vp)
{
    int t = blockIdx.x * 256 + threadIdx.x;       // NV*8 threads total
    int v  = t >> 3;
    int hb = (t & 7) * 8;
    const float* fr = vf + (size_t)v * NH + hb;
    const float* pr = vp + (size_t)v * NH + hb;
    float4 fa = *(const float4*)fr;
    float4 fb = *(const float4*)(fr + 4);
    float4 pa = *(const float4*)pr;
    float4 pb = *(const float4*)(pr + 4);
    float f[8] = {fa.x, fa.y, fa.z, fa.w, fb.x, fb.y, fb.z, fb.w};
    float p[8] = {pa.x, pa.y, pa.z, pa.w, pb.x, pb.y, pb.z, pb.w};

    __align__(16) __nv_bfloat16 hi8[8], lo8[8], cs8[8], sn8[8];
    float s2 = 0.f;
    #pragma unroll
    for (int i = 0; i < 8; i++) {
        s2 = fmaf(f[i], f[i], s2);
        __nv_bfloat16 h = __float2bfloat16(f[i]);
        hi8[i] = h;
        lo8[i] = __float2bfloat16(f[i] - __bfloat162float(h));
        float sn, cs;
        sincosf(p[i], &sn, &cs);
        cs8[i] = __float2bfloat16(cs);
        sn8[i] = __float2bfloat16(sn);
    }
    size_t base = (size_t)v * KK + hb;
    *(uint4*)(g_Bh + base)        = *(uint4*)hi8;
    *(uint4*)(g_Bh + base + 64)   = *(uint4*)cs8;
    *(uint4*)(g_Bh + base + 128)  = *(uint4*)sn8;
    *(uint4*)(g_Bl + (size_t)v * 64 + hb) = *(uint4*)lo8;

    s2 += __shfl_down_sync(0xffffffffu, s2, 4);
    s2 += __shfl_down_sync(0xffffffffu, s2, 2);
    s2 += __shfl_down_sync(0xffffffffu, s2, 1);
    if ((t & 7) == 0) g_v2[v] = s2;
}

// B cols [192,448) = Wv^T (Wv is [256][32000]); packed 8B stores
__global__ void wv_transpose(const float* __restrict__ Wv)
{
    __shared__ float st[32][33];    // st[v-local][k-local]
    const int v0 = blockIdx.x * 32;
    const int k0 = blockIdx.y * 32;
    const int tx = threadIdx.x, ty = threadIdx.y;   // (32, 8)
    #pragma unroll
    for (int r = 0; r < 4; r++)
        st[tx][ty + r * 8] = Wv[(size_t)(k0 + ty + r * 8) * NV + v0 + tx];
    __syncthreads();
    int tid = ty * 32 + tx;
    int vl = tid >> 3, kg = tid & 7;
    __align__(8) __nv_bfloat16 pk[4];
    #pragma unroll
    for (int j = 0; j < 4; j++)
        pk[j] = __float2bfloat16(st[vl][kg * 4 + j]);
    *(uint2*)(g_Bh + (size_t)(v0 + vl) * KK + 192 + k0 + kg * 4) = *(uint2*)pk;
}

// ---------------------------------------------------------------------------
// Main GEMM on mma.sync.m16n8k16.
// CTA 128x128, 8 warps (2M x 4N), warp tile 64x32, 96KB smem -> 2 CTAs/SM.
// 3-buffer rotation with lo-overlay: chunk 0 -> stage0 (+ lo planes in the
// overlay region); chunk c>=1 -> {stage1, overlay, stage0}[(c-1)%3].
// One __syncthreads per chunk; prefetch depth 2.
// ---------------------------------------------------------------------------
__device__ __forceinline__ uint32_t stage_off(int c) {
    if (c == 0) return 0u;
    int r = (c - 1) % 3;
    return (r == 0) ? (uint32_t)STAGE_BYTES
         : (r == 1) ? (uint32_t)(2 * STAGE_BYTES) : 0u;
}

__global__ void __launch_bounds__(256, 2)
spectral_hmma(const float* __restrict__ bv, float* __restrict__ out)
{
    extern __shared__ char smem[];
    const uint32_t sbase = smem_u32(smem);

    const int tid = threadIdx.x;
    const int wid = tid >> 5;
    const int lid = tid & 31;
    const int wm = wid & 1;          // M offset wm*64
    const int wn = wid >> 1;         // 0..3 -> N offset wn*32
    const int v0 = blockIdx.x * CTA_N;
    const int m0 = blockIdx.y * CTA_M;

    const int a_row = lid & 15;
    const int a_c16 = (lid >> 4) & 1;
    const int b_row = ((lid >> 4) & 1) * 8 + (lid & 7);
    const int b_c16 = (lid >> 3) & 1;

    float acc[4][4][4];
    #pragma unroll
    for (int mt = 0; mt < 4; mt++)
        #pragma unroll
        for (int nt = 0; nt < 4; nt++)
            #pragma unroll
            for (int e = 0; e < 4; e++) acc[mt][nt][e] = 0.f;

    // hi-plane loader: A 128 rows + B 128 rows (128B rows, SW128)
    auto load_hi = [&](uint32_t stoff, int kc) {
        const uint32_t sb = sbase + stoff;
        #pragma unroll
        for (int i = 0; i < 4; i++) {
            int idx = tid + i * 256;
            int r = idx >> 3, u = idx & 7;
            uint32_t so = (uint32_t)(r * 128 + ((u * 16) ^ ((r & 7) << 4)));
            cpa16(sb + so, g_Ah + (size_t)(m0 + r) * KK + kc + u * 8);
        }
        #pragma unroll
        for (int i = 0; i < 4; i++) {
            int idx = tid + i * 256;
            int r = idx >> 3, u = idx & 7;
            uint32_t so = (uint32_t)(r * 128 + ((u * 16) ^ ((r & 7) << 4)));
            cpa16(sb + OFF_BH + so, g_Bh + (size_t)(v0 + r) * KK + kc + u * 8);
        }
    };
    auto load_lo = [&]() {
        #pragma unroll
        for (int i = 0; i < 4; i++) {
            int idx = tid + i * 256;
            int r = idx >> 3, u = idx & 7;
            uint32_t so = (uint32_t)(r * 128 + ((u * 16) ^ ((r & 7) << 4)));
            cpa16(sbase + OFF_AL + so, g_Al + (size_t)(m0 + r) * 64 + u * 8);
        }
        #pragma unroll
        for (int i = 0; i < 4; i++) {
            int idx = tid + i * 256;
            int r = idx >> 3, u = idx & 7;
            uint32_t so = (uint32_t)(r * 128 + ((u * 16) ^ ((r & 7) << 4)));
            cpa16(sbase + OFF_BL + so, g_Bl + (size_t)(v0 + r) * 64 + u * 8);
        }
    };

    // prologue: G0 = chunk0 hi + lo;  G1 = chunk1 hi
    load_hi(0, 0);
    load_lo();
    CPA_COMMIT();
    load_hi(STAGE_BYTES, KC);
    CPA_COMMIT();

    #pragma unroll 1
    for (int c = 0; c < NCHUNK; c++) {
        // ensure chunk c's group has landed
        if (c == 1 || c == NCHUNK - 1) { CPA_WAIT0(); } else { CPA_WAIT1(); }
        __syncthreads();   // all threads' copies visible; prev compute done

        // prefetch (overlay region is free from chunk 1 onward)
        if (c == 1) {
            load_hi(2 * STAGE_BYTES, 2 * KC); CPA_COMMIT();   // chunk 2 -> overlay
            load_hi(0, 3 * KC);               CPA_COMMIT();   // chunk 3 -> stage0
        } else if (c >= 2 && c + 2 < NCHUNK) {
            load_hi(stage_off(c + 2), (c + 2) * KC); CPA_COMMIT();
        }

        const uint32_t sb = sbase + stage_off(c);

        if (c == 0) {
            // 3-product split chunk (hi from stage0, lo from overlay region)
            #pragma unroll
            for (int ks = 0; ks < 4; ks++) {
                uint32_t ah[4][4], al[4][4], bh[2][4], bl[2][4];
                #pragma unroll
                for (int mt = 0; mt < 4; mt++) {
                    int R = wm * 64 + mt * 16 + a_row;
                    uint32_t kpat = (uint32_t)((ks * 32 + a_c16 * 16) ^ ((R & 7) << 4));
                    LDSM_X4(ah[mt], sb + (uint32_t)(R * 128) + kpat);
                    LDSM_X4(al[mt], sbase + OFF_AL + (uint32_t)(R * 128) + kpat);
                }
                #pragma unroll
                for (int ng = 0; ng < 2; ng++) {
                    int R = wn * 32 + ng * 16 + b_row;
                    uint32_t kpat = (uint32_t)((ks * 32 + b_c16 * 16) ^ ((R & 7) << 4));
                    LDSM_X4(bh[ng], sb + OFF_BH + (uint32_t)(R * 128) + kpat);
                    LDSM_X4(bl[ng], sbase + OFF_BL + (uint32_t)(R * 128) + kpat);
                }
                #pragma unroll
                for (int mt = 0; mt < 4; mt++)
                    #pragma unroll
                    for (int nt = 0; nt < 4; nt++) {
                        int ng = nt >> 1, sub = nt & 1;
                        MMA16816(acc[mt][nt], ah[mt], bh[ng][sub * 2], bh[ng][sub * 2 + 1]);
                        MMA16816(acc[mt][nt], ah[mt], bl[ng][sub * 2], bl[ng][sub * 2 + 1]);
                        MMA16816(acc[mt][nt], al[mt], bh[ng][sub * 2], bh[ng][sub * 2 + 1]);
                    }
            }
            // transform: acc <- 0.1*bv - sqrt(max(f2+v2-2*acc,0))*lam
            #pragma unroll
            for (int mt = 0; mt < 4; mt++) {
                int r0 = m0 + wm * 64 + mt * 16 + (lid >> 2);
                int r1 = r0 + 8;
                float f2a = g_f2[r0],  lma = g_lamp[r0];
                float f2b = g_f2[r1],  lmb = g_lamp[r1];
                #pragma unroll
                for (int nt = 0; nt < 4; nt++) {
                    int c0 = v0 + wn * 32 + (nt >> 1) * 16 + (nt & 1) * 8 + 2 * (lid & 3);
                    float v2x = g_v2[c0],     bvx = 0.1f * bv[c0];
                    float v2y = g_v2[c0 + 1], bvy = 0.1f * bv[c0 + 1];
                    float* a = acc[mt][nt];
                    a[0] = bvx - sqrtf(fmaxf(f2a + v2x - 2.f * a[0], 0.f)) * lma;
                    a[1] = bvy - sqrtf(fmaxf(f2a + v2y - 2.f * a[1], 0.f)) * lma;
                    a[2] = bvx - sqrtf(fmaxf(f2b + v2x - 2.f * a[2], 0.f)) * lmb;
                    a[3] = bvy - sqrtf(fmaxf(f2b + v2y - 2.f * a[3], 0.f)) * lmb;
                }
            }
        } else {
            // single-product hi*hi chunks
            #pragma unroll
            for (int ks = 0; ks < 4; ks++) {
                uint32_t ah[4][4], bh[2][4];
                #pragma unroll
                for (int mt = 0; mt < 4; mt++) {
                    int R = wm * 64 + mt * 16 + a_row;
                    uint32_t off = (uint32_t)(R * 128 + ((ks * 32 + a_c16 * 16) ^ ((R & 7) << 4)));
                    LDSM_X4(ah[mt], sb + off);
                }
                #pragma unroll
                for (int ng = 0; ng < 2; ng++) {
                    int R = wn * 32 + ng * 16 + b_row;
                    uint32_t off = (uint32_t)(R * 128 + ((ks * 32 + b_c16 * 16) ^ ((R & 7) << 4)));
                    LDSM_X4(bh[ng], sb + OFF_BH + off);
                }
                #pragma unroll
                for (int mt = 0; mt < 4; mt++)
                    #pragma unroll
                    for (int nt = 0; nt < 4; nt++) {
                        int ng = nt >> 1, sub = nt & 1;
                        MMA16816(acc[mt][nt], ah[mt], bh[ng][sub * 2], bh[ng][sub * 2 + 1]);
                    }
            }
        }
    }

    // Writeout
    #pragma unroll
    for (int mt = 0; mt < 4; mt++) {
        size_t r0 = (size_t)(m0 + wm * 64 + mt * 16 + (lid >> 2));
        #pragma unroll
        for (int nt = 0; nt < 4; nt++) {
            int c0 = v0 + wn * 32 + (nt >> 1) * 16 + (nt & 1) * 8 + 2 * (lid & 3);
            float2 lo = make_float2(acc[mt][nt][0], acc[mt][nt][1]);
            float2 hi = make_float2(acc[mt][nt][2], acc[mt][nt][3]);
            *(float2*)(out + r0 * NV + c0)       = lo;
            *(float2*)(out + (r0 + 8) * NV + c0) = hi;
        }
    }
}

// ---------------------------------------------------------------------------
extern "C" void kernel_launch(void* const* d_in, const int* in_sizes, int n_in,
                              void* d_out, int out_size)
{
    const float* wave = (const float*)d_in[0];   // (2,1024,192)
    const float* vf   = (const float*)d_in[1];   // (32000,64)
    const float* vp   = (const float*)d_in[2];   // (32000,64)
    const float* W0   = (const float*)d_in[3];   // (192,256)
    const float* b0   = (const float*)d_in[4];
    const float* W1   = (const float*)d_in[5];   // (256,256)
    const float* b1   = (const float*)d_in[6];
    const float* W2   = (const float*)d_in[7];   // (256,256)
    const float* b2   = (const float*)d_in[8];
    const float* Wv   = (const float*)d_in[9];   // (256,32000)
    const float* bv   = (const float*)d_in[10];  // (32000,)
    const float* rw   = (const float*)d_in[11];  // (3,)
    float* out = (float*)d_out;

    cudaFuncSetAttribute(spectral_hmma,
                         cudaFuncAttributeMaxDynamicSharedMemorySize, SMEM_TOTAL);

    token_prep<<<NT / 4, 256>>>(wave, W0, b0, W1, b1, W2, b2, rw);
    vocab_feat<<<NV * 8 / 256, 256>>>(vf, vp);
    wv_transpose<<<dim3(NV / 32, 256 / 32), dim3(32, 8)>>>(Wv);
    spectral_hmma<<<dim3(NV / CTA_N, NT / CTA_M), 256, SMEM_TOTAL>>>(bv, out);
}

// round 14
// speedup vs baseline: 2.0476x; 1.0846x over previous
#include <cuda_runtime.h>
#include <cuda_bf16.h>
#include <math.h>
#include <stdint.h>

// ---------------------------------------------------------------------------
// Problem constants
// ---------------------------------------------------------------------------
static constexpr int NT = 2048;      // tokens (B*L)
static constexpr int NH = 64;
static constexpr int NV = 32000;
static constexpr int KK = 448;       // 64 freq + 64 cos + 64 sin + 256 hidden

// GEMM tiling
static constexpr int CTA_M = 128;
static constexpr int CTA_N = 128;
static constexpr int KC    = 64;               // K per chunk
static constexpr int NCHUNK = KK / KC;         // 7

// SMEM layout (bytes). Rows are 128B (64 bf16), SW128-swizzled.
static constexpr int AH_BYTES = CTA_M * KC * 2;   // 16384
static constexpr int BH_BYTES = CTA_N * KC * 2;   // 16384
static constexpr int STAGE_BYTES = AH_BYTES + BH_BYTES;          // 32768
static constexpr int OFF_BH  = AH_BYTES;                          // within stage
static constexpr int OFF_AL  = 2 * STAGE_BYTES;                   // 65536
static constexpr int OFF_BL  = 2 * STAGE_BYTES + AH_BYTES;        // 81920
static constexpr int SMEM_TOTAL = 3 * STAGE_BYTES;                // 98304 -> 2 CTAs/SM

// prep_fused block ranges
static constexpr int NB_TOK = NT / 4;                 // 512
static constexpr int NB_VOC = NV * 8 / 256;           // 1000
static constexpr int NB_WVT = (NV / 32) * (256 / 32); // 8000
static constexpr int NB_PREP = NB_TOK + NB_VOC + NB_WVT;

// ---------------------------------------------------------------------------
// Device scratch (allocation-free).  lo planes exist only for K in [0,64).
// ---------------------------------------------------------------------------
__device__ __nv_bfloat16 g_Ah[NT * KK];
__device__ __nv_bfloat16 g_Al[NT * 64];
__device__ __nv_bfloat16 g_Bh[(size_t)NV * KK];
__device__ __nv_bfloat16 g_Bl[(size_t)NV * 64];
__device__ float g_v2[NV];
__device__ float g_f2[NT];
__device__ float g_lamp[NT];

// ---------------------------------------------------------------------------
// Helpers
// ---------------------------------------------------------------------------
__device__ __forceinline__ uint32_t smem_u32(const void* p) {
    uint32_t a;
    asm("{ .reg .u64 t; cvta.to.shared.u64 t, %1; cvt.u32.u64 %0, t; }" : "=r"(a) : "l"(p));
    return a;
}

__device__ __forceinline__ void cpa16(uint32_t saddr, const void* gaddr) {
    asm volatile("cp.async.cg.shared.global [%0], [%1], 16;" :: "r"(saddr), "l"(gaddr));
}
#define CPA_COMMIT() asm volatile("cp.async.commit_group;" ::: "memory")
#define CPA_WAIT1()  asm volatile("cp.async.wait_group 1;" ::: "memory")
#define CPA_WAIT0()  asm volatile("cp.async.wait_group 0;" ::: "memory")

#define LDSM_X4(r, addr) \
    asm volatile("ldmatrix.sync.aligned.m8n8.x4.shared.b16 {%0,%1,%2,%3}, [%4];" \
        : "=r"((r)[0]), "=r"((r)[1]), "=r"((r)[2]), "=r"((r)[3]) : "r"(addr))

#define MMA16816(C, A, B0, B1) \
    asm volatile("mma.sync.aligned.m16n8k16.row.col.f32.bf16.bf16.f32 " \
        "{%0,%1,%2,%3}, {%4,%5,%6,%7}, {%8,%9}, {%0,%1,%2,%3};" \
        : "+f"((C)[0]), "+f"((C)[1]), "+f"((C)[2]), "+f"((C)[3]) \
        : "r"((A)[0]), "r"((A)[1]), "r"((A)[2]), "r"((A)[3]), "r"(B0), "r"(B1))

__device__ __forceinline__ float gelu_exact(float x) {
    return 0.5f * x * (1.0f + erff(x * 0.7071067811865476f));
}

// ---------------------------------------------------------------------------
// Fused prep kernel: one launch, three block-range branches.
//   [0, 512)        token MLP + trig -> g_Ah/g_Al, g_f2, g_lamp
//   [512, 1512)     vocab features   -> g_Bh/g_Bl cols [0,192), g_v2
//   [1512, 9512)    Wv transpose     -> g_Bh cols [192,448)
// ---------------------------------------------------------------------------
__global__ void __launch_bounds__(256)
prep_fused(const float* __restrict__ wave,
           const float* __restrict__ W0, const float* __restrict__ b0,
           const float* __restrict__ W1, const float* __restrict__ b1,
           const float* __restrict__ W2, const float* __restrict__ b2,
           const float* __restrict__ rw,
           const float* __restrict__ vf, const float* __restrict__ vp,
           const float* __restrict__ Wv)
{
    const int bid = blockIdx.x;

    if (bid < NB_TOK) {
        // ---------------- token prep: 4 tokens / block ----------------
        __shared__ float sw[4][192];
        __shared__ float sx[4][256];
        __shared__ float sy[4][256];
        __shared__ float slamp[4];

        const int t0 = bid * 4;
        const int j  = threadIdx.x;

        for (int i = j; i < 4 * 192; i += 256) {
            int tok = i / 192, kk = i % 192;
            sw[tok][kk] = wave[(size_t)(t0 + tok) * 192 + kk];
        }
        __syncthreads();

        if (j < 8) {
            int tok = j & 3;
            if (j < 4) {
                float s = 0.f;
                for (int h = 0; h < NH; h++) { float f = sw[tok][h]; s += f * f; }
                g_f2[t0 + tok] = s;
            } else {
                float s = 0.f;
                for (int h = 0; h < NH; h++) s += sw[tok][64 + h];
                float l = log1pf(s);
                slamp[tok] = l;
                g_lamp[t0 + tok] = l;
            }
        }

        float acc0 = 0.f, acc1 = 0.f, acc2 = 0.f, acc3 = 0.f;
        float bb = b0[j];
        for (int k = 0; k < 192; k++) {
            float w = W0[k * 256 + j];
            acc0 = fmaf(sw[0][k], w, acc0);
            acc1 = fmaf(sw[1][k], w, acc1);
            acc2 = fmaf(sw[2][k], w, acc2);
            acc3 = fmaf(sw[3][k], w, acc3);
        }
        __syncthreads();
        sx[0][j] = gelu_exact(acc0 + bb);
        sx[1][j] = gelu_exact(acc1 + bb);
        sx[2][j] = gelu_exact(acc2 + bb);
        sx[3][j] = gelu_exact(acc3 + bb);
        __syncthreads();

        bb = b1[j];
        float r1 = rw[1];
        acc0 = acc1 = acc2 = acc3 = 0.f;
        for (int k = 0; k < 256; k++) {
            float w = W1[k * 256 + j];
            acc0 = fmaf(sx[0][k], w, acc0);
            acc1 = fmaf(sx[1][k], w, acc1);
            acc2 = fmaf(sx[2][k], w, acc2);
            acc3 = fmaf(sx[3][k], w, acc3);
        }
        sy[0][j] = gelu_exact(acc0 + bb) + r1 * sx[0][j];
        sy[1][j] = gelu_exact(acc1 + bb) + r1 * sx[1][j];
        sy[2][j] = gelu_exact(acc2 + bb) + r1 * sx[2][j];
        sy[3][j] = gelu_exact(acc3 + bb) + r1 * sx[3][j];
        __syncthreads();

        bb = b2[j];
        float r2 = rw[2];
        acc0 = acc1 = acc2 = acc3 = 0.f;
        for (int k = 0; k < 256; k++) {
            float w = W2[k * 256 + j];
            acc0 = fmaf(sy[0][k], w, acc0);
            acc1 = fmaf(sy[1][k], w, acc1);
            acc2 = fmaf(sy[2][k], w, acc2);
            acc3 = fmaf(sy[3][k], w, acc3);
        }
        {
            float z[4];
            z[0] = 0.1f * (gelu_exact(acc0 + bb) + r2 * sy[0][j]);
            z[1] = 0.1f * (gelu_exact(acc1 + bb) + r2 * sy[1][j]);
            z[2] = 0.1f * (gelu_exact(acc2 + bb) + r2 * sy[2][j]);
            z[3] = 0.1f * (gelu_exact(acc3 + bb) + r2 * sy[3][j]);
            #pragma unroll
            for (int i = 0; i < 4; i++)
                g_Ah[(size_t)(t0 + i) * KK + 192 + j] = __float2bfloat16(z[i]);
        }
        {
            int i = j >> 6, h = j & 63;
            float f  = sw[i][h];
            float ph = sw[i][128 + h];
            float sc = 0.0078125f * slamp[i];
            float sn, cs;
            sincosf(ph, &sn, &cs);
            size_t base = (size_t)(t0 + i) * KK;
            __nv_bfloat16 fh = __float2bfloat16(f);
            g_Ah[base + h] = fh;
            g_Al[(size_t)(t0 + i) * 64 + h] = __float2bfloat16(f - __bfloat162float(fh));
            g_Ah[base + 64 + h]  = __float2bfloat16(cs * sc);
            g_Ah[base + 128 + h] = __float2bfloat16(sn * sc);
        }
    } else if (bid < NB_TOK + NB_VOC) {
        // ---------------- vocab features: 8 threads / row ----------------
        int t = (bid - NB_TOK) * 256 + threadIdx.x;
        int v  = t >> 3;
        int hb = (t & 7) * 8;
        const float* fr = vf + (size_t)v * NH + hb;
        const float* pr = vp + (size_t)v * NH + hb;
        float4 fa = *(const float4*)fr;
        float4 fb = *(const float4*)(fr + 4);
        float4 pa = *(const float4*)pr;
        float4 pb = *(const float4*)(pr + 4);
        float f[8] = {fa.x, fa.y, fa.z, fa.w, fb.x, fb.y, fb.z, fb.w};
        float p[8] = {pa.x, pa.y, pa.z, pa.w, pb.x, pb.y, pb.z, pb.w};

        __align__(16) __nv_bfloat16 hi8[8], lo8[8], cs8[8], sn8[8];
        float s2 = 0.f;
        #pragma unroll
        for (int i = 0; i < 8; i++) {
            s2 = fmaf(f[i], f[i], s2);
            __nv_bfloat16 h = __float2bfloat16(f[i]);
            hi8[i] = h;
            lo8[i] = __float2bfloat16(f[i] - __bfloat162float(h));
            float sn, cs;
            sincosf(p[i], &sn, &cs);
            cs8[i] = __float2bfloat16(cs);
            sn8[i] = __float2bfloat16(sn);
        }
        size_t base = (size_t)v * KK + hb;
        *(uint4*)(g_Bh + base)        = *(uint4*)hi8;
        *(uint4*)(g_Bh + base + 64)   = *(uint4*)cs8;
        *(uint4*)(g_Bh + base + 128)  = *(uint4*)sn8;
        *(uint4*)(g_Bl + (size_t)v * 64 + hb) = *(uint4*)lo8;

        s2 += __shfl_down_sync(0xffffffffu, s2, 4);
        s2 += __shfl_down_sync(0xffffffffu, s2, 2);
        s2 += __shfl_down_sync(0xffffffffu, s2, 1);
        if ((t & 7) == 0) g_v2[v] = s2;
    } else {
        // ---------------- Wv transpose: 32x32 tile / block ----------------
        __shared__ float st[32][33];    // st[v-local][k-local]
        int wb = bid - NB_TOK - NB_VOC;
        const int v0 = (wb / 8) * 32;
        const int k0 = (wb % 8) * 32;
        const int tx = threadIdx.x & 31, ty = threadIdx.x >> 5;   // (32, 8)
        #pragma unroll
        for (int r = 0; r < 4; r++)
            st[tx][ty + r * 8] = Wv[(size_t)(k0 + ty + r * 8) * NV + v0 + tx];
        __syncthreads();
        int tid = threadIdx.x;
        int vl = tid >> 3, kg = tid & 7;
        __align__(8) __nv_bfloat16 pk[4];
        #pragma unroll
        for (int j = 0; j < 4; j++)
            pk[j] = __float2bfloat16(st[vl][kg * 4 + j]);
        *(uint2*)(g_Bh + (size_t)(v0 + vl) * KK + 192 + k0 + kg * 4) = *(uint2*)pk;
    }
}

// ---------------------------------------------------------------------------
// Main GEMM on mma.sync.m16n8k16.  (unchanged from R10 champion)
// CTA 128x128, 8 warps (2M x 4N), warp tile 64x32, 96KB smem -> 2 CTAs/SM.
// 3-buffer rotation with lo-overlay; one __syncthreads per chunk.
// ---------------------------------------------------------------------------
__device__ __forceinline__ uint32_t stage_off(int c) {
    if (c == 0) return 0u;
    int r = (c - 1) % 3;
    return (r == 0) ? (uint32_t)STAGE_BYTES
         : (r == 1) ? (uint32_t)(2 * STAGE_BYTES) : 0u;
}

__global__ void __launch_bounds__(256, 2)
spectral_hmma(const float* __restrict__ bv, float* __restrict__ out)
{
    extern __shared__ char smem[];
    const uint32_t sbase = smem_u32(smem);

    const int tid = threadIdx.x;
    const int wid = tid >> 5;
    const int lid = tid & 31;
    const int wm = wid & 1;          // M offset wm*64
    const int wn = wid >> 1;         // 0..3 -> N offset wn*32
    const int v0 = blockIdx.x * CTA_N;
    const int m0 = blockIdx.y * CTA_M;

    const int a_row = lid & 15;
    const int a_c16 = (lid >> 4) & 1;
    const int b_row = ((lid >> 4) & 1) * 8 + (lid & 7);
    const int b_c16 = (lid >> 3) & 1;

    float acc[4][4][4];
    #pragma unroll
    for (int mt = 0; mt < 4; mt++)
        #pragma unroll
        for (int nt = 0; nt < 4; nt++)
            #pragma unroll
            for (int e = 0; e < 4; e++) acc[mt][nt][e] = 0.f;

    auto load_hi = [&](uint32_t stoff, int kc) {
        const uint32_t sb = sbase + stoff;
        #pragma unroll
        for (int i = 0; i < 4; i++) {
            int idx = tid + i * 256;
            int r = idx >> 3, u = idx & 7;
            uint32_t so = (uint32_t)(r * 128 + ((u * 16) ^ ((r & 7) << 4)));
            cpa16(sb + so, g_Ah + (size_t)(m0 + r) * KK + kc + u * 8);
        }
        #pragma unroll
        for (int i = 0; i < 4; i++) {
            int idx = tid + i * 256;
            int r = idx >> 3, u = idx & 7;
            uint32_t so = (uint32_t)(r * 128 + ((u * 16) ^ ((r & 7) << 4)));
            cpa16(sb + OFF_BH + so, g_Bh + (size_t)(v0 + r) * KK + kc + u * 8);
        }
    };
    auto load_lo = [&]() {
        #pragma unroll
        for (int i = 0; i < 4; i++) {
            int idx = tid + i * 256;
            int r = idx >> 3, u = idx & 7;
            uint32_t so = (uint32_t)(r * 128 + ((u * 16) ^ ((r & 7) << 4)));
            cpa16(sbase + OFF_AL + so, g_Al + (size_t)(m0 + r) * 64 + u * 8);
        }
        #pragma unroll
        for (int i = 0; i < 4; i++) {
            int idx = tid + i * 256;
            int r = idx >> 3, u = idx & 7;
            uint32_t so = (uint32_t)(r * 128 + ((u * 16) ^ ((r & 7) << 4)));
            cpa16(sbase + OFF_BL + so, g_Bl + (size_t)(v0 + r) * 64 + u * 8);
        }
    };

    // prologue: G0 = chunk0 hi + lo;  G1 = chunk1 hi
    load_hi(0, 0);
    load_lo();
    CPA_COMMIT();
    load_hi(STAGE_BYTES, KC);
    CPA_COMMIT();

    #pragma unroll 1
    for (int c = 0; c < NCHUNK; c++) {
        if (c == 1 || c == NCHUNK - 1) { CPA_WAIT0(); } else { CPA_WAIT1(); }
        __syncthreads();

        if (c == 1) {
            load_hi(2 * STAGE_BYTES, 2 * KC); CPA_COMMIT();   // chunk 2 -> overlay
            load_hi(0, 3 * KC);               CPA_COMMIT();   // chunk 3 -> stage0
        } else if (c >= 2 && c + 2 < NCHUNK) {
            load_hi(stage_off(c + 2), (c + 2) * KC); CPA_COMMIT();
        }

        const uint32_t sb = sbase + stage_off(c);

        if (c == 0) {
            #pragma unroll
            for (int ks = 0; ks < 4; ks++) {
                uint32_t ah[4][4], al[4][4], bh[2][4], bl[2][4];
                #pragma unroll
                for (int mt = 0; mt < 4; mt++) {
                    int R = wm * 64 + mt * 16 + a_row;
                    uint32_t kpat = (uint32_t)((ks * 32 + a_c16 * 16) ^ ((R & 7) << 4));
                    LDSM_X4(ah[mt], sb + (uint32_t)(R * 128) + kpat);
                    LDSM_X4(al[mt], sbase + OFF_AL + (uint32_t)(R * 128) + kpat);
                }
                #pragma unroll
                for (int ng = 0; ng < 2; ng++) {
                    int R = wn * 32 + ng * 16 + b_row;
                    uint32_t kpat = (uint32_t)((ks * 32 + b_c16 * 16) ^ ((R & 7) << 4));
                    LDSM_X4(bh[ng], sb + OFF_BH + (uint32_t)(R * 128) + kpat);
                    LDSM_X4(bl[ng], sbase + OFF_BL + (uint32_t)(R * 128) + kpat);
                }
                #pragma unroll
                for (int mt = 0; mt < 4; mt++)
                    #pragma unroll
                    for (int nt = 0; nt < 4; nt++) {
                        int ng = nt >> 1, sub = nt & 1;
                        MMA16816(acc[mt][nt], ah[mt], bh[ng][sub * 2], bh[ng][sub * 2 + 1]);
                        MMA16816(acc[mt][nt], ah[mt], bl[ng][sub * 2], bl[ng][sub * 2 + 1]);
                        MMA16816(acc[mt][nt], al[mt], bh[ng][sub * 2], bh[ng][sub * 2 + 1]);
                    }
            }
            // transform: acc <- 0.1*bv - sqrt(max(f2+v2-2*acc,0))*lam
            #pragma unroll
            for (int mt = 0; mt < 4; mt++) {
                int r0 = m0 + wm * 64 + mt * 16 + (lid >> 2);
                int r1 = r0 + 8;
                float f2a = g_f2[r0],  lma = g_lamp[r0];
                float f2b = g_f2[r1],  lmb = g_lamp[r1];
                #pragma unroll
                for (int nt = 0; nt < 4; nt++) {
                    int c0 = v0 + wn * 32 + (nt >> 1) * 16 + (nt & 1) * 8 + 2 * (lid & 3);
                    float v2x = g_v2[c0],     bvx = 0.1f * bv[c0];
                    float v2y = g_v2[c0 + 1], bvy = 0.1f * bv[c0 + 1];
                    float* a = acc[mt][nt];
                    a[0] = bvx - sqrtf(fmaxf(f2a + v2x - 2.f * a[0], 0.f)) * lma;
                    a[1] = bvy - sqrtf(fmaxf(f2a + v2y - 2.f * a[1], 0.f)) * lma;
                    a[2] = bvx - sqrtf(fmaxf(f2b + v2x - 2.f * a[2], 0.f)) * lmb;
                    a[3] = bvy - sqrtf(fmaxf(f2b + v2y - 2.f * a[3], 0.f)) * lmb;
                }
            }
        } else {
            #pragma unroll
            for (int ks = 0; ks < 4; ks++) {
                uint32_t ah[4][4], bh[2][4];
                #pragma unroll
                for (int mt = 0; mt < 4; mt++) {
                    int R = wm * 64 + mt * 16 + a_row;
                    uint32_t off = (uint32_t)(R * 128 + ((ks * 32 + a_c16 * 16) ^ ((R & 7) << 4)));
                    LDSM_X4(ah[mt], sb + off);
                }
                #pragma unroll
                for (int ng = 0; ng < 2; ng++) {
                    int R = wn * 32 + ng * 16 + b_row;
                    uint32_t off = (uint32_t)(R * 128 + ((ks * 32 + b_c16 * 16) ^ ((R & 7) << 4)));
                    LDSM_X4(bh[ng], sb + OFF_BH + off);
                }
                #pragma unroll
                for (int mt = 0; mt < 4; mt++)
                    #pragma unroll
                    for (int nt = 0; nt < 4; nt++) {
                        int ng = nt >> 1, sub = nt & 1;
                        MMA16816(acc[mt][nt], ah[mt], bh[ng][sub * 2], bh[ng][sub * 2 + 1]);
                    }
            }
        }
    }

    // Writeout
    #pragma unroll
    for (int mt = 0; mt < 4; mt++) {
        size_t r0 = (size_t)(m0 + wm * 64 + mt * 16 + (lid >> 2));
        #pragma unroll
        for (int nt = 0; nt < 4; nt++) {
            int c0 = v0 + wn * 32 + (nt >> 1) * 16 + (nt & 1) * 8 + 2 * (lid & 3);
            float2 lo = make_float2(acc[mt][nt][0], acc[mt][nt][1]);
            float2 hi = make_float2(acc[mt][nt][2], acc[mt][nt][3]);
            *(float2*)(out + r0 * NV + c0)       = lo;
            *(float2*)(out + (r0 + 8) * NV + c0) = hi;
        }
    }
}

// ---------------------------------------------------------------------------
extern "C" void kernel_launch(void* const* d_in, const int* in_sizes, int n_in,
                              void* d_out, int out_size)
{
    const float* wave = (const float*)d_in[0];   // (2,1024,192)
    const float* vf   = (const float*)d_in[1];   // (32000,64)
    const float* vp   = (const float*)d_in[2];   // (32000,64)
    const float* W0   = (const float*)d_in[3];   // (192,256)
    const float* b0   = (const float*)d_in[4];
    const float* W1   = (const float*)d_in[5];   // (256,256)
    const float* b1   = (const float*)d_in[6];
    const float* W2   = (const float*)d_in[7];   // (256,256)
    const float* b2   = (const float*)d_in[8];
    const float* Wv   = (const float*)d_in[9];   // (256,32000)
    const float* bv   = (const float*)d_in[10];  // (32000,)
    const float* rw   = (const float*)d_in[11];  // (3,)
    float* out = (float*)d_out;

    cudaFuncSetAttribute(spectral_hmma,
                         cudaFuncAttributeMaxDynamicSharedMemorySize, SMEM_TOTAL);

    prep_fused<<<NB_PREP, 256>>>(wave, W0, b0, W1, b1, W2, b2, rw, vf, vp, Wv);
    spectral_hmma<<<dim3(NV / CTA_N, NT / CTA_M), 256, SMEM_TOTAL>>>(bv, out);
}

// round 16
// speedup vs baseline: 2.0777x; 1.0147x over previous
#include <cuda_runtime.h>
#include <cuda_fp16.h>
#include <math.h>
#include <stdint.h>

// ---------------------------------------------------------------------------
// Problem constants
// ---------------------------------------------------------------------------
static constexpr int NT = 2048;      // tokens (B*L)
static constexpr int NH = 64;
static constexpr int NV = 32000;
static constexpr int KK = 448;       // 64 freq + 64 cos + 64 sin + 256 hidden

// GEMM tiling
static constexpr int CTA_M = 128;
static constexpr int CTA_N = 128;
static constexpr int KC    = 64;               // K per chunk
static constexpr int NCHUNK = KK / KC;         // 7

// SMEM: three rotating 32KB stages (A 16KB + B 16KB), SW128-swizzled 128B rows.
static constexpr int AH_BYTES = CTA_M * KC * 2;   // 16384
static constexpr int BH_BYTES = CTA_N * KC * 2;   // 16384
static constexpr int STAGE_BYTES = AH_BYTES + BH_BYTES;          // 32768
static constexpr int OFF_BH  = AH_BYTES;
static constexpr int SMEM_TOTAL = 3 * STAGE_BYTES;               // 98304 -> 2 CTAs/SM

// prep_fused block ranges
static constexpr int NB_TOK = NT / 4;                 // 512
static constexpr int NB_VOC = NV * 8 / 256;           // 1000
static constexpr int NB_WVT = (NV / 32) * (256 / 32); // 8000
static constexpr int NB_PREP = NB_TOK + NB_VOC + NB_WVT;

// ---------------------------------------------------------------------------
// Device scratch (allocation-free).  Everything fp16, single plane.
// ---------------------------------------------------------------------------
__device__ __half g_A[NT * KK];
__device__ __half g_B[(size_t)NV * KK];
__device__ float g_v2[NV];     // from QUANTIZED vocab freqs
__device__ float g_f2[NT];     // from QUANTIZED token freqs
__device__ float g_lamp[NT];

// ---------------------------------------------------------------------------
// Helpers
// ---------------------------------------------------------------------------
__device__ __forceinline__ uint32_t smem_u32(const void* p) {
    uint32_t a;
    asm("{ .reg .u64 t; cvta.to.shared.u64 t, %1; cvt.u32.u64 %0, t; }" : "=r"(a) : "l"(p));
    return a;
}

__device__ __forceinline__ void cpa16(uint32_t saddr, const void* gaddr) {
    asm volatile("cp.async.cg.shared.global [%0], [%1], 16;" :: "r"(saddr), "l"(gaddr));
}
#define CPA_COMMIT() asm volatile("cp.async.commit_group;" ::: "memory")
#define CPA_WAIT1()  asm volatile("cp.async.wait_group 1;" ::: "memory")
#define CPA_WAIT0()  asm volatile("cp.async.wait_group 0;" ::: "memory")

#define LDSM_X4(r, addr) \
    asm volatile("ldmatrix.sync.aligned.m8n8.x4.shared.b16 {%0,%1,%2,%3}, [%4];" \
        : "=r"((r)[0]), "=r"((r)[1]), "=r"((r)[2]), "=r"((r)[3]) : "r"(addr))

#define MMA16816(C, A, B0, B1) \
    asm volatile("mma.sync.aligned.m16n8k16.row.col.f32.f16.f16.f32 " \
        "{%0,%1,%2,%3}, {%4,%5,%6,%7}, {%8,%9}, {%0,%1,%2,%3};" \
        : "+f"((C)[0]), "+f"((C)[1]), "+f"((C)[2]), "+f"((C)[3]) \
        : "r"((A)[0]), "r"((A)[1]), "r"((A)[2]), "r"((A)[3]), "r"(B0), "r"(B1))

__device__ __forceinline__ float gelu_exact(float x) {
    return 0.5f * x * (1.0f + erff(x * 0.7071067811865476f));
}

// ---------------------------------------------------------------------------
// Fused prep kernel: one launch, three block-range branches.
//   [0, 512)        token MLP + trig -> g_A, g_f2 (quantized), g_lamp
//   [512, 1512)     vocab features   -> g_B cols [0,192), g_v2 (quantized)
//   [1512, 9512)    Wv transpose     -> g_B cols [192,448)
// A row layout [t][448]: [0,64)=freq, [64,128)=cos(ph)*sc, [128,192)=sin(ph)*sc,
// [192,448)=0.1*x.   sc = (0.5/64)*log1p(sum amps)
// ---------------------------------------------------------------------------
__global__ void __launch_bounds__(256)
prep_fused(const float* __restrict__ wave,
           const float* __restrict__ W0, const float* __restrict__ b0,
           const float* __restrict__ W1, const float* __restrict__ b1,
           const float* __restrict__ W2, const float* __restrict__ b2,
           const float* __restrict__ rw,
           const float* __restrict__ vf, const float* __restrict__ vp,
           const float* __restrict__ Wv)
{
    const int bid = blockIdx.x;

    if (bid < NB_TOK) {
        // ---------------- token prep: 4 tokens / block ----------------
        __shared__ float sw[4][192];
        __shared__ float sx[4][256];
        __shared__ float sy[4][256];
        __shared__ float slamp[4];

        const int t0 = bid * 4;
        const int j  = threadIdx.x;

        for (int i = j; i < 4 * 192; i += 256) {
            int tok = i / 192, kk = i % 192;
            sw[tok][kk] = wave[(size_t)(t0 + tok) * 192 + kk];
        }
        __syncthreads();

        if (j < 8) {
            int tok = j & 3;
            if (j < 4) {
                // f2 from QUANTIZED freqs so the cross term is an exact
                // distance between quantized vectors (no cancellation error)
                float s = 0.f;
                for (int h = 0; h < NH; h++) {
                    float q = __half2float(__float2half_rn(sw[tok][h]));
                    s = fmaf(q, q, s);
                }
                g_f2[t0 + tok] = s;
            } else {
                float s = 0.f;
                for (int h = 0; h < NH; h++) s += sw[tok][64 + h];
                float l = log1pf(s);
                slamp[tok] = l;
                g_lamp[t0 + tok] = l;
            }
        }

        float acc0 = 0.f, acc1 = 0.f, acc2 = 0.f, acc3 = 0.f;
        float bb = b0[j];
        for (int k = 0; k < 192; k++) {
            float w = W0[k * 256 + j];
            acc0 = fmaf(sw[0][k], w, acc0);
            acc1 = fmaf(sw[1][k], w, acc1);
            acc2 = fmaf(sw[2][k], w, acc2);
            acc3 = fmaf(sw[3][k], w, acc3);
        }
        __syncthreads();
        sx[0][j] = gelu_exact(acc0 + bb);
        sx[1][j] = gelu_exact(acc1 + bb);
        sx[2][j] = gelu_exact(acc2 + bb);
        sx[3][j] = gelu_exact(acc3 + bb);
        __syncthreads();

        bb = b1[j];
        float r1 = rw[1];
        acc0 = acc1 = acc2 = acc3 = 0.f;
        for (int k = 0; k < 256; k++) {
            float w = W1[k * 256 + j];
            acc0 = fmaf(sx[0][k], w, acc0);
            acc1 = fmaf(sx[1][k], w, acc1);
            acc2 = fmaf(sx[2][k], w, acc2);
            acc3 = fmaf(sx[3][k], w, acc3);
        }
        sy[0][j] = gelu_exact(acc0 + bb) + r1 * sx[0][j];
        sy[1][j] = gelu_exact(acc1 + bb) + r1 * sx[1][j];
        sy[2][j] = gelu_exact(acc2 + bb) + r1 * sx[2][j];
        sy[3][j] = gelu_exact(acc3 + bb) + r1 * sx[3][j];
        __syncthreads();

        bb = b2[j];
        float r2 = rw[2];
        acc0 = acc1 = acc2 = acc3 = 0.f;
        for (int k = 0; k < 256; k++) {
            float w = W2[k * 256 + j];
            acc0 = fmaf(sy[0][k], w, acc0);
            acc1 = fmaf(sy[1][k], w, acc1);
            acc2 = fmaf(sy[2][k], w, acc2);
            acc3 = fmaf(sy[3][k], w, acc3);
        }
        {
            float z[4];
            z[0] = 0.1f * (gelu_exact(acc0 + bb) + r2 * sy[0][j]);
            z[1] = 0.1f * (gelu_exact(acc1 + bb) + r2 * sy[1][j]);
            z[2] = 0.1f * (gelu_exact(acc2 + bb) + r2 * sy[2][j]);
            z[3] = 0.1f * (gelu_exact(acc3 + bb) + r2 * sy[3][j]);
            #pragma unroll
            for (int i = 0; i < 4; i++)
                g_A[(size_t)(t0 + i) * KK + 192 + j] = __float2half_rn(z[i]);
        }
        {
            int i = j >> 6, h = j & 63;
            float f  = sw[i][h];
            float ph = sw[i][128 + h];
            float sc = 0.0078125f * slamp[i];
            float sn, cs;
            sincosf(ph, &sn, &cs);
            size_t base = (size_t)(t0 + i) * KK;
            g_A[base + h]        = __float2half_rn(f);
            g_A[base + 64 + h]   = __float2half_rn(cs * sc);
            g_A[base + 128 + h]  = __float2half_rn(sn * sc);
        }
    } else if (bid < NB_TOK + NB_VOC) {
        // ---------------- vocab features: 8 threads / row ----------------
        int t = (bid - NB_TOK) * 256 + threadIdx.x;
        int v  = t >> 3;
        int hb = (t & 7) * 8;
        const float* fr = vf + (size_t)v * NH + hb;
        const float* pr = vp + (size_t)v * NH + hb;
        float4 fa = *(const float4*)fr;
        float4 fb = *(const float4*)(fr + 4);
        float4 pa = *(const float4*)pr;
        float4 pb = *(const float4*)(pr + 4);
        float f[8] = {fa.x, fa.y, fa.z, fa.w, fb.x, fb.y, fb.z, fb.w};
        float p[8] = {pa.x, pa.y, pa.z, pa.w, pb.x, pb.y, pb.z, pb.w};

        __align__(16) __half hi8[8], cs8[8], sn8[8];
        float s2 = 0.f;
        #pragma unroll
        for (int i = 0; i < 8; i++) {
            __half h = __float2half_rn(f[i]);
            hi8[i] = h;
            float q = __half2float(h);      // v2 from QUANTIZED value
            s2 = fmaf(q, q, s2);
            float sn, cs;
            sincosf(p[i], &sn, &cs);
            cs8[i] = __float2half_rn(cs);
            sn8[i] = __float2half_rn(sn);
        }
        size_t base = (size_t)v * KK + hb;
        *(uint4*)(g_B + base)        = *(uint4*)hi8;
        *(uint4*)(g_B + base + 64)   = *(uint4*)cs8;
        *(uint4*)(g_B + base + 128)  = *(uint4*)sn8;

        s2 += __shfl_down_sync(0xffffffffu, s2, 4);
        s2 += __shfl_down_sync(0xffffffffu, s2, 2);
        s2 += __shfl_down_sync(0xffffffffu, s2, 1);
        if ((t & 7) == 0) g_v2[v] = s2;
    } else {
        // ---------------- Wv transpose: 32x32 tile / block ----------------
        __shared__ float st[32][33];    // st[v-local][k-local]
        int wb = bid - NB_TOK - NB_VOC;
        const int v0 = (wb / 8) * 32;
        const int k0 = (wb % 8) * 32;
        const int tx = threadIdx.x & 31, ty = threadIdx.x >> 5;
        #pragma unroll
        for (int r = 0; r < 4; r++)
            st[tx][ty + r * 8] = Wv[(size_t)(k0 + ty + r * 8) * NV + v0 + tx];
        __syncthreads();
        int tid = threadIdx.x;
        int vl = tid >> 3, kg = tid & 7;
        __align__(8) __half pk[4];
        #pragma unroll
        for (int j = 0; j < 4; j++)
            pk[j] = __float2half_rn(st[vl][kg * 4 + j]);
        *(uint2*)(g_B + (size_t)(v0 + vl) * KK + 192 + k0 + kg * 4) = *(uint2*)pk;
    }
}

// ---------------------------------------------------------------------------
// Main GEMM on mma.sync.m16n8k16 fp16 (single product, K=448 uniform).
// CTA 128x128, 8 warps (2M x 4N), warp tile 64x32, 96KB -> 2 CTAs/SM.
// Three rotating 32KB stages, prefetch depth 2, one barrier per chunk.
// After chunk 0 (cross term): acc <- 0.1*bv - sqrt(max(f2+v2-2*acc,0))*lam,
// then chunks 1-6 accumulate the linear terms on top.
// ---------------------------------------------------------------------------
__global__ void __launch_bounds__(256, 2)
spectral_hmma(const float* __restrict__ bv, float* __restrict__ out)
{
    extern __shared__ char smem[];
    const uint32_t sbase = smem_u32(smem);

    const int tid = threadIdx.x;
    const int wid = tid >> 5;
    const int lid = tid & 31;
    const int wm = wid & 1;          // M offset wm*64
    const int wn = wid >> 1;         // 0..3 -> N offset wn*32
    const int v0 = blockIdx.x * CTA_N;
    const int m0 = blockIdx.y * CTA_M;

    const int a_row = lid & 15;
    const int a_c16 = (lid >> 4) & 1;
    const int b_row = ((lid >> 4) & 1) * 8 + (lid & 7);
    const int b_c16 = (lid >> 3) & 1;

    float acc[4][4][4];
    #pragma unroll
    for (int mt = 0; mt < 4; mt++)
        #pragma unroll
        for (int nt = 0; nt < 4; nt++)
            #pragma unroll
            for (int e = 0; e < 4; e++) acc[mt][nt][e] = 0.f;

    auto load_stage = [&](uint32_t stoff, int kc) {
        const uint32_t sb = sbase + stoff;
        #pragma unroll
        for (int i = 0; i < 4; i++) {
            int idx = tid + i * 256;
            int r = idx >> 3, u = idx & 7;
            uint32_t so = (uint32_t)(r * 128 + ((u * 16) ^ ((r & 7) << 4)));
            cpa16(sb + so, g_A + (size_t)(m0 + r) * KK + kc + u * 8);
        }
        #pragma unroll
        for (int i = 0; i < 4; i++) {
            int idx = tid + i * 256;
            int r = idx >> 3, u = idx & 7;
            uint32_t so = (uint32_t)(r * 128 + ((u * 16) ^ ((r & 7) << 4)));
            cpa16(sb + OFF_BH + so, g_B + (size_t)(v0 + r) * KK + kc + u * 8);
        }
        CPA_COMMIT();
    };

    // prologue: chunks 0,1 into stages 0,1
    load_stage(0, 0);
    load_stage(STAGE_BYTES, KC);

    #pragma unroll 1
    for (int c = 0; c < NCHUNK; c++) {
        if (c < NCHUNK - 1) { CPA_WAIT1(); } else { CPA_WAIT0(); }
        __syncthreads();   // chunk c visible; all warps done with stage (c-1)%3

        if (c + 2 < NCHUNK)
            load_stage((uint32_t)(((c + 2) % 3) * STAGE_BYTES), (c + 2) * KC);

        const uint32_t sb = sbase + (uint32_t)((c % 3) * STAGE_BYTES);

        #pragma unroll
        for (int ks = 0; ks < 4; ks++) {
            uint32_t ah[4][4], bh[2][4];
            #pragma unroll
            for (int mt = 0; mt < 4; mt++) {
                int R = wm * 64 + mt * 16 + a_row;
                uint32_t off = (uint32_t)(R * 128 + ((ks * 32 + a_c16 * 16) ^ ((R & 7) << 4)));
                LDSM_X4(ah[mt], sb + off);
            }
            #pragma unroll
            for (int ng = 0; ng < 2; ng++) {
                int R = wn * 32 + ng * 16 + b_row;
                uint32_t off = (uint32_t)(R * 128 + ((ks * 32 + b_c16 * 16) ^ ((R & 7) << 4)));
                LDSM_X4(bh[ng], sb + OFF_BH + off);
            }
            #pragma unroll
            for (int mt = 0; mt < 4; mt++)
                #pragma unroll
                for (int nt = 0; nt < 4; nt++) {
                    int ng = nt >> 1, sub = nt & 1;
                    MMA16816(acc[mt][nt], ah[mt], bh[ng][sub * 2], bh[ng][sub * 2 + 1]);
                }
        }

        if (c == 0) {
            // acc = cross (exact quantized distances).  Transform:
            //   acc <- 0.1*bv - sqrt(max(f2+v2-2*acc,0))*lam
            #pragma unroll
            for (int mt = 0; mt < 4; mt++) {
                int r0 = m0 + wm * 64 + mt * 16 + (lid >> 2);
                int r1 = r0 + 8;
                float f2a = g_f2[r0],  lma = g_lamp[r0];
                float f2b = g_f2[r1],  lmb = g_lamp[r1];
                #pragma unroll
                for (int nt = 0; nt < 4; nt++) {
                    int c0 = v0 + wn * 32 + (nt >> 1) * 16 + (nt & 1) * 8 + 2 * (lid & 3);
                    float v2x = g_v2[c0],     bvx = 0.1f * bv[c0];
                    float v2y = g_v2[c0 + 1], bvy = 0.1f * bv[c0 + 1];
                    float* a = acc[mt][nt];
                    a[0] = bvx - sqrtf(fmaxf(f2a + v2x - 2.f * a[0], 0.f)) * lma;
                    a[1] = bvy - sqrtf(fmaxf(f2a + v2y - 2.f * a[1], 0.f)) * lma;
                    a[2] = bvx - sqrtf(fmaxf(f2b + v2x - 2.f * a[2], 0.f)) * lmb;
                    a[3] = bvy - sqrtf(fmaxf(f2b + v2y - 2.f * a[3], 0.f)) * lmb;
                }
            }
        }
    }

    // Writeout
    #pragma unroll
    for (int mt = 0; mt < 4; mt++) {
        size_t r0 = (size_t)(m0 + wm * 64 + mt * 16 + (lid >> 2));
        #pragma unroll
        for (int nt = 0; nt < 4; nt++) {
            int c0 = v0 + wn * 32 + (nt >> 1) * 16 + (nt & 1) * 8 + 2 * (lid & 3);
            float2 lo = make_float2(acc[mt][nt][0], acc[mt][nt][1]);
            float2 hi = make_float2(acc[mt][nt][2], acc[mt][nt][3]);
            *(float2*)(out + r0 * NV + c0)       = lo;
            *(float2*)(out + (r0 + 8) * NV + c0) = hi;
        }
    }
}

// ---------------------------------------------------------------------------
extern "C" void kernel_launch(void* const* d_in, const int* in_sizes, int n_in,
                              void* d_out, int out_size)
{
    const float* wave = (const float*)d_in[0];   // (2,1024,192)
    const float* vf   = (const float*)d_in[1];   // (32000,64)
    const float* vp   = (const float*)d_in[2];   // (32000,64)
    const float* W0   = (const float*)d_in[3];   // (192,256)
    const float* b0   = (const float*)d_in[4];
    const float* W1   = (const float*)d_in[5];   // (256,256)
    const float* b1   = (const float*)d_in[6];
    const float* W2   = (const float*)d_in[7];   // (256,256)
    const float* b2   = (const float*)d_in[8];
    const float* Wv   = (const float*)d_in[9];   // (256,32000)
    const float* bv   = (const float*)d_in[10];  // (32000,)
    const float* rw   = (const float*)d_in[11];  // (3,)
    float* out = (float*)d_out;

    cudaFuncSetAttribute(spectral_hmma,
                         cudaFuncAttributeMaxDynamicSharedMemorySize, SMEM_TOTAL);

    prep_fused<<<NB_PREP, 256>>>(wave, W0, b0, W1, b1, W2, b2, rw, vf, vp, Wv);
    spectral_hmma<<<dim3(NV / CTA_N, NT / CTA_M), 256, SMEM_TOTAL>>>(bv, out);
}